// round 2
// baseline (speedup 1.0000x reference)
#include <cuda_runtime.h>

#define RESV 0.16f
#define XMINV (-51.2f)
#define YMINV (-51.2f)
#define EPSV 1e-5f
#define NEGV (-1.0e9f)

// Folded weights (BN fused, layer-1 algebraically collapsed)
__device__ float g_Wx[64], g_Wy[64], g_Wz[64], g_Wr[64];
__device__ float g_Wxc[64], g_Wyc[64], g_Wzm[64], g_b1f[64];
__device__ float g_W2f[64 * 64], g_b2f[64];
__device__ int g_is64;

__global__ void prep_kernel(const float* __restrict__ W1, const float* __restrict__ b1,
                            const float* __restrict__ g1, const float* __restrict__ beta1,
                            const float* __restrict__ m1, const float* __restrict__ v1,
                            const float* __restrict__ W2, const float* __restrict__ b2,
                            const float* __restrict__ g2, const float* __restrict__ beta2,
                            const float* __restrict__ m2, const float* __restrict__ v2,
                            const unsigned* __restrict__ coords_raw, int n_words) {
    int c = threadIdx.x;  // 0..63
    if (c == 0) g_is64 = 1;
    __syncthreads();
    // dtype sniff: int64 storage of small nonneg values => odd 32-bit words all 0
    int nz = 0;
    for (int i = 2 * c + 1; i < n_words; i += 128) nz |= (coords_raw[i] != 0u);
    if (nz) g_is64 = 0;

    float a1 = g1[c] * rsqrtf(v1[c] + EPSV);
    float w0 = W1[0 * 64 + c], w1 = W1[1 * 64 + c], w2 = W1[2 * 64 + c];
    float w3 = W1[3 * 64 + c], w4 = W1[4 * 64 + c], w5 = W1[5 * 64 + c];
    float w6 = W1[6 * 64 + c], w7 = W1[7 * 64 + c], w8 = W1[8 * 64 + c];
    g_Wx[c]  = (w0 + w4 + w7) * a1;   // x: rows 0, 4(xo), 7(xo)
    g_Wy[c]  = (w1 + w5 + w8) * a1;   // y: rows 1, 5(yo), 8(yo)
    g_Wz[c]  = (w2 + w6) * a1;        // z: rows 2, 6(zo)
    g_Wr[c]  = w3 * a1;
    g_Wxc[c] = (w4 + w7) * a1;        // subtract xc * this
    g_Wyc[c] = (w5 + w8) * a1;        // subtract yc * this
    g_Wzm[c] = w6 * a1;               // subtract zmean * this
    g_b1f[c] = (b1[c] - m1[c]) * a1 + beta1[c];

    float a2 = g2[c] * rsqrtf(v2[c] + EPSV);
    for (int k = 0; k < 64; k++) g_W2f[k * 64 + c] = W2[k * 64 + c] * a2;
    g_b2f[c] = (b2[c] - m2[c]) * a2 + beta2[c];
}

__device__ __forceinline__ void fma2(unsigned long long& d, unsigned long long a,
                                     unsigned long long b) {
    asm("fma.rn.f32x2 %0, %1, %2, %0;" : "+l"(d) : "l"(a), "l"(b));
}
__device__ __forceinline__ unsigned long long add2(unsigned long long a, unsigned long long b) {
    unsigned long long r;
    asm("add.rn.f32x2 %0, %1, %2;" : "=l"(r) : "l"(a), "l"(b));
    return r;
}

__global__ void __launch_bounds__(128)
pfn_main(const float4* __restrict__ pillars,
         const void* __restrict__ coords_raw,
         const void* __restrict__ npts_raw,
         float* __restrict__ out, int P) {
    __shared__ float4 s_pts[32];
    __shared__ float s_h1[32 * 64];
    __shared__ float s_zmean;
    __shared__ float s_red[128];

    const int tid = threadIdx.x;
    const int c = tid & 63;      // output channel
    const int half = tid >> 6;   // which half of the points
    const int is64 = g_is64;

    // W2f column c packed into 32 x b64 registers (pairs over k)
    unsigned long long w2[32];
#pragma unroll
    for (int j = 0; j < 32; j++) {
        float lo = g_W2f[(2 * j) * 64 + c];
        float hi = g_W2f[(2 * j + 1) * 64 + c];
        asm("mov.b64 %0, {%1, %2};" : "=l"(w2[j]) : "f"(lo), "f"(hi));
    }
    const float wX = g_Wx[c], wY = g_Wy[c], wZ = g_Wz[c], wR = g_Wr[c];
    const float wXC = g_Wxc[c], wYC = g_Wyc[c], wZM = g_Wzm[c];
    const float b1c = g_b1f[c], b2c = g_b2f[c];

    for (int p = blockIdx.x; p < P; p += gridDim.x) {
        int npts;
        long long ccol, crow;
        if (is64) {
            npts = (int)((const long long*)npts_raw)[p];
            ccol = ((const long long*)coords_raw)[2 * p + 1];
            crow = ((const long long*)coords_raw)[2 * p];
        } else {
            npts = ((const int*)npts_raw)[p];
            ccol = (long long)((const int*)coords_raw)[2 * p + 1];
            crow = (long long)((const int*)coords_raw)[2 * p];
        }
        if (tid < 32 && tid < npts) s_pts[tid] = pillars[(size_t)p * 32 + tid];
        if (tid < 32) {
            float z = (tid < npts) ? s_pts[tid].z : 0.0f;
#pragma unroll
            for (int o = 16; o; o >>= 1) z += __shfl_xor_sync(0xffffffffu, z, o);
            if (tid == 0) s_zmean = z / fmaxf((float)npts, 1.0f);
        }
        __syncthreads();

        const float zmean = s_zmean;
        const float xcv = ((float)ccol + 0.5f) * RESV + XMINV;
        const float ycv = ((float)crow + 0.5f) * RESV + YMINV;
        float Kc = b1c - xcv * wXC;
        Kc -= ycv * wYC;
        Kc -= zmean * wZM;

        // Layer 1: h1[m][c] for valid points only
        for (int m = half; m < npts; m += 2) {
            float4 pt = s_pts[m];
            float h = fmaf(pt.x, wX, Kc);
            h = fmaf(pt.y, wY, h);
            h = fmaf(pt.z, wZ, h);
            h = fmaf(pt.w, wR, h);
            s_h1[m * 64 + c] = fmaxf(h, 0.0f);
        }
        __syncthreads();

        // Layer 2 (packed f32x2 FMA) + running max over valid points
        float best = NEGV;
        for (int m = half; m < npts; m += 2) {
            const float* hrow = s_h1 + m * 64;
            unsigned long long a0 = 0ull, a1 = 0ull, a2 = 0ull, a3 = 0ull;
#pragma unroll
            for (int j = 0; j < 8; j++) {
                ulonglong2 h0 = *(const ulonglong2*)(hrow + j * 8);
                ulonglong2 h1 = *(const ulonglong2*)(hrow + j * 8 + 4);
                fma2(a0, h0.x, w2[j * 4 + 0]);
                fma2(a1, h0.y, w2[j * 4 + 1]);
                fma2(a2, h1.x, w2[j * 4 + 2]);
                fma2(a3, h1.y, w2[j * 4 + 3]);
            }
            unsigned long long s = add2(add2(a0, a1), add2(a2, a3));
            float lo, hi;
            asm("mov.b64 {%0, %1}, %2;" : "=f"(lo), "=f"(hi) : "l"(s));
            float v = lo + hi + b2c;
            v = fmaxf(v, 0.0f);
            best = fmaxf(best, v);
        }
        s_red[tid] = best;
        __syncthreads();
        if (tid < 64) out[(size_t)p * 64 + c] = fmaxf(s_red[c], s_red[64 + c]);
        // next iteration's first __syncthreads() orders s_red/s_h1 reuse
    }
}

extern "C" void kernel_launch(void* const* d_in, const int* in_sizes, int n_in,
                              void* d_out, int out_size) {
    const float* pillars = (const float*)d_in[0];
    const void*  coords  = d_in[1];
    const void*  npts    = d_in[2];
    const float* W1 = (const float*)d_in[3];
    const float* b1 = (const float*)d_in[4];
    const float* g1 = (const float*)d_in[5];
    const float* be1 = (const float*)d_in[6];
    const float* m1 = (const float*)d_in[7];
    const float* v1 = (const float*)d_in[8];
    const float* W2 = (const float*)d_in[9];
    const float* b2 = (const float*)d_in[10];
    const float* g2 = (const float*)d_in[11];
    const float* be2 = (const float*)d_in[12];
    const float* m2 = (const float*)d_in[13];
    const float* v2 = (const float*)d_in[14];

    int P = in_sizes[0] / 128;  // P * M(32) * 4
    int n_words = 2 * P < 4096 ? 2 * P : 4096;  // safe in both dtype cases

    prep_kernel<<<1, 64>>>(W1, b1, g1, be1, m1, v1, W2, b2, g2, be2, m2, v2,
                           (const unsigned*)coords, n_words);

    int grid = 1184;  // ~8 blocks/SM worth of grid-stride work, balanced tail
    if (grid > P) grid = P;
    pfn_main<<<grid, 128>>>((const float4*)pillars, coords, npts, (float*)d_out, P);
}

// round 5
// speedup vs baseline: 1.9967x; 1.9967x over previous
#include <cuda_runtime.h>
#include <cuda_bf16.h>
#include <cstdint>

typedef unsigned long long u64;

#define RESV 0.16f
#define XMINV (-51.2f)
#define YMINV (-51.2f)
#define EPSV 1e-5f
#define NEGV (-1.0e9f)

// ---------------- folded weights ----------------
__device__ float4 g_w1pack[64];   // {Wx,Wy,Wz,Wr}*a1 per channel
__device__ float4 g_k1pack[64];   // {b1f, Wxc, Wyc, Wzm}
__device__ float  g_b2f[64];
__device__ unsigned g_W2hi[2048]; // W2^T row c (n), k-major bf16x2 words (hi part)
__device__ unsigned g_W2lo[2048]; // (lo residual)
__device__ int g_is64;

__global__ void prep_kernel(const float* __restrict__ W1, const float* __restrict__ b1,
                            const float* __restrict__ g1, const float* __restrict__ beta1,
                            const float* __restrict__ m1, const float* __restrict__ v1,
                            const float* __restrict__ W2, const float* __restrict__ b2,
                            const float* __restrict__ g2, const float* __restrict__ beta2,
                            const float* __restrict__ m2, const float* __restrict__ v2,
                            const unsigned* __restrict__ coords_raw, int n_words) {
    int c = threadIdx.x;  // 0..63
    if (c == 0) g_is64 = 1;
    __syncthreads();
    int nz = 0;
    for (int i = 2 * c + 1; i < n_words; i += 128) nz |= (coords_raw[i] != 0u);
    if (nz) g_is64 = 0;

    float a1 = g1[c] * rsqrtf(v1[c] + EPSV);
    float w0 = W1[0*64+c], w1 = W1[1*64+c], w2v = W1[2*64+c];
    float w3 = W1[3*64+c], w4 = W1[4*64+c], w5 = W1[5*64+c];
    float w6 = W1[6*64+c], w7 = W1[7*64+c], w8 = W1[8*64+c];
    g_w1pack[c] = make_float4((w0+w4+w7)*a1, (w1+w5+w8)*a1, (w2v+w6)*a1, w3*a1);
    g_k1pack[c] = make_float4((b1[c]-m1[c])*a1 + beta1[c], (w4+w7)*a1, (w5+w8)*a1, w6*a1);

    float a2 = g2[c] * rsqrtf(v2[c] + EPSV);
    g_b2f[c] = (b2[c] - m2[c]) * a2 + beta2[c];
    for (int j = 0; j < 32; j++) {
        float v0  = W2[(2*j)   * 64 + c] * a2;
        float v1b = W2[(2*j+1) * 64 + c] * a2;
        unsigned h0 = (unsigned)__bfloat16_as_ushort(__float2bfloat16(v0));
        unsigned h1 = (unsigned)__bfloat16_as_ushort(__float2bfloat16(v1b));
        float r0 = v0  - __uint_as_float(h0 << 16);
        float r1 = v1b - __uint_as_float(h1 << 16);
        unsigned l0 = (unsigned)__bfloat16_as_ushort(__float2bfloat16(r0));
        unsigned l1 = (unsigned)__bfloat16_as_ushort(__float2bfloat16(r1));
        g_W2hi[c * 32 + j] = h0 | (h1 << 16);
        g_W2lo[c * 32 + j] = l0 | (l1 << 16);
    }
}

// ---------------- helpers ----------------
__device__ __forceinline__ uint32_t smem_u32(const void* p) {
    uint32_t a;
    asm("{ .reg .u64 t; cvta.to.shared.u64 t, %1; cvt.u32.u64 %0, t; }" : "=r"(a) : "l"(p));
    return a;
}
__device__ __forceinline__ void fma2(u64& d, u64 a, u64 b) {
    asm("fma.rn.f32x2 %0, %1, %2, %0;" : "+l"(d) : "l"(a), "l"(b));
}
__device__ __forceinline__ u64 pack2(float lo, float hi) {
    u64 r;
    asm("mov.b64 %0, {%1, %2};" : "=l"(r) : "f"(lo), "f"(hi));
    return r;
}
__device__ __forceinline__ void ldm4(unsigned* r, uint32_t a) {
    asm volatile("ldmatrix.sync.aligned.m8n8.x4.shared.b16 {%0,%1,%2,%3}, [%4];"
        : "=r"(r[0]), "=r"(r[1]), "=r"(r[2]), "=r"(r[3]) : "r"(a));
}
__device__ __forceinline__ void mma_bf16(float* c, const unsigned* a, unsigned b0, unsigned b1) {
    asm("mma.sync.aligned.m16n8k16.row.col.f32.bf16.bf16.f32 "
        "{%0,%1,%2,%3}, {%4,%5,%6,%7}, {%8,%9}, {%0,%1,%2,%3};"
        : "+f"(c[0]), "+f"(c[1]), "+f"(c[2]), "+f"(c[3])
        : "r"(a[0]), "r"(a[1]), "r"(a[2]), "r"(a[3]), "r"(b0), "r"(b1));
}

// ---------------- smem layout ----------------
#define OFF_L1W   0        // float4[64]: pairs {wx01,wy01},{wz01,wr01}
#define OFF_L1K   1024     // float4[64]: pairs {b1f01,wxc01},{wyc01,wzm01}
#define OFF_KC    2048     // float[4*64]
#define OFF_W2HI  3072     // 64 rows x 144B
#define OFF_W2LO  12288
#define OFF_H1    21504    // 4 warps x (hi 32x144 + lo 32x144)
#define H1_WARP   9216
#define SMEM_BYTES 58368

__global__ void __launch_bounds__(128)
pfn_main(const float4* __restrict__ pillars,
         const void* __restrict__ coords_raw,
         const void* __restrict__ npts_raw,
         float* __restrict__ out, int P) {
    extern __shared__ char smem[];
    const int tid = threadIdx.x;
    const int wid = tid >> 5;
    const int lane = tid & 31;
    const int is64 = g_is64;

    float4* s_l1w = (float4*)(smem + OFF_L1W);
    float4* s_l1k = (float4*)(smem + OFF_L1K);
    float*  s_kc  = (float*)(smem + OFF_KC);

    // ---- stage weights to smem (once) ----
    for (int i = tid; i < 2048; i += 128) {
        int n = i >> 5, j = i & 31;
        ((unsigned*)(smem + OFF_W2HI))[n * 36 + j] = g_W2hi[i];
        ((unsigned*)(smem + OFF_W2LO))[n * 36 + j] = g_W2lo[i];
    }
    if (tid < 32) {
        float4 u = g_w1pack[2*tid], v = g_w1pack[2*tid+1];
        s_l1w[2*tid]   = make_float4(u.x, v.x, u.y, v.y);
        s_l1w[2*tid+1] = make_float4(u.z, v.z, u.w, v.w);
        float4 a = g_k1pack[2*tid], b = g_k1pack[2*tid+1];
        s_l1k[2*tid]   = make_float4(a.x, b.x, a.y, b.y);
        s_l1k[2*tid+1] = make_float4(a.z, b.z, a.w, b.w);
    }
    __syncthreads();

    const uint32_t ub = smem_u32(smem);
    const uint32_t aoff = (uint32_t)((lane & 15) * 144 + ((lane >> 4) << 4));
    const uint32_t gg = (uint32_t)(lane >> 3), rr = (uint32_t)(lane & 7);
    const uint32_t boff = (((gg >> 1) << 3) + rr) * 144 + ((gg & 1) << 4);
    const uint32_t Ahi = ub + OFF_H1 + wid * H1_WARP + aoff;
    const uint32_t Alo = Ahi + 4608;
    const uint32_t Bhi = ub + OFF_W2HI + boff;
    const uint32_t Blo = ub + OFF_W2LO + boff;
    char* h1hi_row = smem + OFF_H1 + wid * H1_WARP + lane * 144;
    char* h1lo_row = h1hi_row + 4608;

    for (int p = blockIdx.x * 4 + wid; p < P; p += gridDim.x * 4) {
        // ---- pillar meta (uniform loads) + point ----
        int np; long long rw, cl;
        if (is64) {
            np = (int)((const long long*)npts_raw)[p];
            rw = ((const long long*)coords_raw)[2 * p];
            cl = ((const long long*)coords_raw)[2 * p + 1];
        } else {
            np = ((const int*)npts_raw)[p];
            rw = (long long)((const int*)coords_raw)[2 * p];
            cl = (long long)((const int*)coords_raw)[2 * p + 1];
        }
        const float xc = ((float)cl + 0.5f) * RESV + XMINV;
        const float yc = ((float)rw + 0.5f) * RESV + YMINV;
        float4 pt = pillars[(size_t)p * 32 + lane];
        float zs = (lane < np) ? pt.z : 0.f;
#pragma unroll
        for (int o = 16; o; o >>= 1) zs += __shfl_xor_sync(0xffffffffu, zs, o);
        const float zm = zs / fmaxf((float)np, 1.f);

        // ---- per-(pillar,channel-pair) constants: lane t -> channels 2t,2t+1 ----
        {
            float4 ck = s_l1k[2 * lane];
            float4 dk = s_l1k[2 * lane + 1];
            float kc0 = ck.x - xc * ck.z - yc * dk.x - zm * dk.z;
            float kc1 = ck.y - xc * ck.w - yc * dk.y - zm * dk.w;
            *(float2*)(s_kc + (wid << 6) + 2 * lane) = make_float2(kc0, kc1);
        }
        __syncwarp();

        // ---- layer 1: lane = point row; split-bf16 rows to smem ----
        {
            const u64 xx = pack2(pt.x, pt.x), yy = pack2(pt.y, pt.y);
            const u64 zz = pack2(pt.z, pt.z), rr2 = pack2(pt.w, pt.w);
            const float* kcp = s_kc + (wid << 6);
            uint4 bh4, bl4;
#pragma unroll
            for (int j = 0; j < 32; j++) {
                ulonglong2 wab = *(const ulonglong2*)(s_l1w + 2 * j);
                ulonglong2 wcd = *(const ulonglong2*)(s_l1w + 2 * j + 1);
                u64 hp = *(const u64*)(kcp + 2 * j);
                fma2(hp, xx, wab.x); fma2(hp, yy, wab.y);
                fma2(hp, zz, wcd.x); fma2(hp, rr2, wcd.y);
                float h0, h1;
                asm("mov.b64 {%0,%1}, %2;" : "=f"(h0), "=f"(h1) : "l"(hp));
                h0 = fmaxf(h0, 0.f); h1 = fmaxf(h1, 0.f);
                unsigned hw, lw;
                asm("cvt.rn.bf16x2.f32 %0, %1, %2;" : "=r"(hw) : "f"(h1), "f"(h0));
                float e0 = h0 - __uint_as_float(hw << 16);
                float e1 = h1 - __uint_as_float(hw & 0xFFFF0000u);
                asm("cvt.rn.bf16x2.f32 %0, %1, %2;" : "=r"(lw) : "f"(e1), "f"(e0));
                (&bh4.x)[j & 3] = hw;
                (&bl4.x)[j & 3] = lw;
                if ((j & 3) == 3) {
                    *(uint4*)(h1hi_row + (j >> 2) * 16) = bh4;
                    *(uint4*)(h1lo_row + (j >> 2) * 16) = bl4;
                }
            }
        }
        __syncwarp();

        // ---- layer 2: HMMA, 3 split products; n in two halves of 32 channels ----
        const int rbase = lane >> 2;
#pragma unroll
        for (int h = 0; h < 2; h++) {
            float C[2][4][4];
#pragma unroll
            for (int mt = 0; mt < 2; mt++)
#pragma unroll
                for (int nt = 0; nt < 4; nt++)
#pragma unroll
                    for (int i = 0; i < 4; i++) C[mt][nt][i] = 0.f;

#pragma unroll
            for (int ks = 0; ks < 4; ks++) {
                unsigned AH[2][4], AL[2][4], BH[2][4], BL[2][4];
                ldm4(AH[0], Ahi + ks * 32);
                ldm4(AH[1], Ahi + 2304 + ks * 32);
                ldm4(AL[0], Alo + ks * 32);
                ldm4(AL[1], Alo + 2304 + ks * 32);
                uint32_t bb = (uint32_t)(h * 4608 + ks * 32);
                ldm4(BH[0], Bhi + bb);
                ldm4(BH[1], Bhi + bb + 2304);
                ldm4(BL[0], Blo + bb);
                ldm4(BL[1], Blo + bb + 2304);
#pragma unroll
                for (int mt = 0; mt < 2; mt++)
#pragma unroll
                    for (int nt = 0; nt < 4; nt++) {
                        const unsigned* bhp = &BH[nt >> 1][(nt & 1) * 2];
                        const unsigned* blp = &BL[nt >> 1][(nt & 1) * 2];
                        mma_bf16(C[mt][nt], AH[mt], bhp[0], bhp[1]);
                        mma_bf16(C[mt][nt], AH[mt], blp[0], blp[1]);
                        mma_bf16(C[mt][nt], AL[mt], bhp[0], bhp[1]);
                    }
            }

            // ---- epilogue: masked max over points, butterfly, bias+relu ----
            const bool v0 = (rbase < np), v1 = (rbase + 8 < np);
            const bool v2 = (rbase + 16 < np), v3 = (rbase + 24 < np);
#pragma unroll
            for (int nt = 0; nt < 4; nt++) {
                float e = NEGV, o = NEGV;
                if (v0) { e = fmaxf(e, C[0][nt][0]); o = fmaxf(o, C[0][nt][1]); }
                if (v1) { e = fmaxf(e, C[0][nt][2]); o = fmaxf(o, C[0][nt][3]); }
                if (v2) { e = fmaxf(e, C[1][nt][0]); o = fmaxf(o, C[1][nt][1]); }
                if (v3) { e = fmaxf(e, C[1][nt][2]); o = fmaxf(o, C[1][nt][3]); }
#pragma unroll
                for (int off = 4; off <= 16; off <<= 1) {
                    e = fmaxf(e, __shfl_xor_sync(0xffffffffu, e, off));
                    o = fmaxf(o, __shfl_xor_sync(0xffffffffu, o, off));
                }
                if (lane < 4) {
                    int c = (h * 4 + nt) * 8 + 2 * lane;
                    float r0 = (np > 0) ? fmaxf(e + g_b2f[c], 0.f) : NEGV;
                    float r1 = (np > 0) ? fmaxf(o + g_b2f[c + 1], 0.f) : NEGV;
                    out[(size_t)p * 64 + c] = r0;
                    out[(size_t)p * 64 + c + 1] = r1;
                }
            }
        }
        __syncwarp();  // protect h1/kc smem reuse across loop iterations
    }
}

extern "C" void kernel_launch(void* const* d_in, const int* in_sizes, int n_in,
                              void* d_out, int out_size) {
    const float* pillars = (const float*)d_in[0];
    const void*  coords  = d_in[1];
    const void*  npts    = d_in[2];
    const float* W1 = (const float*)d_in[3];
    const float* b1 = (const float*)d_in[4];
    const float* g1 = (const float*)d_in[5];
    const float* be1 = (const float*)d_in[6];
    const float* m1 = (const float*)d_in[7];
    const float* v1 = (const float*)d_in[8];
    const float* W2 = (const float*)d_in[9];
    const float* b2 = (const float*)d_in[10];
    const float* g2 = (const float*)d_in[11];
    const float* be2 = (const float*)d_in[12];
    const float* m2 = (const float*)d_in[13];
    const float* v2 = (const float*)d_in[14];

    int P = in_sizes[0] / 128;
    int n_words = 2 * P < 4096 ? 2 * P : 4096;

    cudaFuncSetAttribute(pfn_main, cudaFuncAttributeMaxDynamicSharedMemorySize, SMEM_BYTES);

    prep_kernel<<<1, 64>>>(W1, b1, g1, be1, m1, v1, W2, b2, g2, be2, m2, v2,
                           (const unsigned*)coords, n_words);

    int grid = 3 * 152;
    int need = (P + 3) / 4;
    if (grid > need) grid = need;
    if (grid < 1) grid = 1;
    pfn_main<<<grid, 128, SMEM_BYTES>>>((const float4*)pillars, coords, npts,
                                        (float*)d_out, P);
}

// round 6
// speedup vs baseline: 2.1246x; 1.0641x over previous
#include <cuda_runtime.h>
#include <cuda_bf16.h>
#include <cstdint>

typedef unsigned long long u64;

#define RESV 0.16f
#define XMINV (-51.2f)
#define YMINV (-51.2f)
#define EPSV 1e-5f
#define NEGV (-1.0e9f)

// ---------------- folded weights ----------------
__device__ float4 g_w1pack[64];   // {Wx,Wy,Wz,Wr}*a1 per channel
__device__ float4 g_k1pack[64];   // {b1f, Wxc, Wyc, Wzm}
__device__ float  g_b2f[64];
__device__ unsigned g_W2hi[2048]; // W2^T row c (n), k-major bf16x2 words (hi part)
__device__ unsigned g_W2lo[2048]; // (lo residual)
__device__ int g_is64;

__global__ void prep_kernel(const float* __restrict__ W1, const float* __restrict__ b1,
                            const float* __restrict__ g1, const float* __restrict__ beta1,
                            const float* __restrict__ m1, const float* __restrict__ v1,
                            const float* __restrict__ W2, const float* __restrict__ b2,
                            const float* __restrict__ g2, const float* __restrict__ beta2,
                            const float* __restrict__ m2, const float* __restrict__ v2,
                            const unsigned* __restrict__ coords_raw, int n_words) {
    int c = threadIdx.x;  // 0..63
    if (c == 0) g_is64 = 1;
    __syncthreads();
    int nz = 0;
    for (int i = 2 * c + 1; i < n_words; i += 128) nz |= (coords_raw[i] != 0u);
    if (nz) g_is64 = 0;

    float a1 = g1[c] * rsqrtf(v1[c] + EPSV);
    float w0 = W1[0*64+c], w1 = W1[1*64+c], w2v = W1[2*64+c];
    float w3 = W1[3*64+c], w4 = W1[4*64+c], w5 = W1[5*64+c];
    float w6 = W1[6*64+c], w7 = W1[7*64+c], w8 = W1[8*64+c];
    g_w1pack[c] = make_float4((w0+w4+w7)*a1, (w1+w5+w8)*a1, (w2v+w6)*a1, w3*a1);
    g_k1pack[c] = make_float4((b1[c]-m1[c])*a1 + beta1[c], (w4+w7)*a1, (w5+w8)*a1, w6*a1);

    float a2 = g2[c] * rsqrtf(v2[c] + EPSV);
    g_b2f[c] = (b2[c] - m2[c]) * a2 + beta2[c];
    for (int j = 0; j < 32; j++) {
        float v0  = W2[(2*j)   * 64 + c] * a2;
        float v1b = W2[(2*j+1) * 64 + c] * a2;
        unsigned h0 = (unsigned)__bfloat16_as_ushort(__float2bfloat16(v0));
        unsigned h1 = (unsigned)__bfloat16_as_ushort(__float2bfloat16(v1b));
        float r0 = v0  - __uint_as_float(h0 << 16);
        float r1 = v1b - __uint_as_float(h1 << 16);
        unsigned l0 = (unsigned)__bfloat16_as_ushort(__float2bfloat16(r0));
        unsigned l1 = (unsigned)__bfloat16_as_ushort(__float2bfloat16(r1));
        g_W2hi[c * 32 + j] = h0 | (h1 << 16);
        g_W2lo[c * 32 + j] = l0 | (l1 << 16);
    }
}

// ---------------- helpers ----------------
__device__ __forceinline__ uint32_t smem_u32(const void* p) {
    uint32_t a;
    asm("{ .reg .u64 t; cvta.to.shared.u64 t, %1; cvt.u32.u64 %0, t; }" : "=r"(a) : "l"(p));
    return a;
}
__device__ __forceinline__ void fma2(u64& d, u64 a, u64 b) {
    asm("fma.rn.f32x2 %0, %1, %2, %0;" : "+l"(d) : "l"(a), "l"(b));
}
__device__ __forceinline__ u64 pack2(float lo, float hi) {
    u64 r;
    asm("mov.b64 %0, {%1, %2};" : "=l"(r) : "f"(lo), "f"(hi));
    return r;
}
__device__ __forceinline__ void ldm4(unsigned* r, uint32_t a) {
    asm volatile("ldmatrix.sync.aligned.m8n8.x4.shared.b16 {%0,%1,%2,%3}, [%4];"
        : "=r"(r[0]), "=r"(r[1]), "=r"(r[2]), "=r"(r[3]) : "r"(a));
}
__device__ __forceinline__ void mma_bf16(float* c, const unsigned* a, unsigned b0, unsigned b1) {
    asm("mma.sync.aligned.m16n8k16.row.col.f32.bf16.bf16.f32 "
        "{%0,%1,%2,%3}, {%4,%5,%6,%7}, {%8,%9}, {%0,%1,%2,%3};"
        : "+f"(c[0]), "+f"(c[1]), "+f"(c[2]), "+f"(c[3])
        : "r"(a[0]), "r"(a[1]), "r"(a[2]), "r"(a[3]), "r"(b0), "r"(b1));
}

// ---------------- smem layout (<=56320B -> 4 CTAs/SM) ----------------
#define OFF_L1W   0        // float4[64]: pairs {wx01,wy01},{wz01,wr01}
#define OFF_L1K   1024     // float4[64]: pairs {b1f01,wxc01},{wyc01,wzm01}
#define OFF_KC    2048     // float[4*64]
#define OFF_W2HI  3072     // 64 rows x 128B, XOR-swizzled chunks
#define OFF_W2LO  11264
#define OFF_H1    19456    // 4 warps x (hi 32x144 + lo 32x144)
#define H1_WARP   9216
#define SMEM_BYTES 56320

__global__ void __launch_bounds__(128)
pfn_main(const float4* __restrict__ pillars,
         const void* __restrict__ coords_raw,
         const void* __restrict__ npts_raw,
         float* __restrict__ out, int P) {
    extern __shared__ char smem[];
    const int tid = threadIdx.x;
    const int wid = tid >> 5;
    const int lane = tid & 31;
    const int is64 = g_is64;

    float4* s_l1w = (float4*)(smem + OFF_L1W);
    float4* s_l1k = (float4*)(smem + OFF_L1K);
    float*  s_kc  = (float*)(smem + OFF_KC);

    // ---- stage weights to smem (once); W2 tiles 128B-stride, chunk^(row&7) swizzle ----
    for (int i = tid; i < 2048; i += 128) {
        int n = i >> 5, j = i & 31;
        int widx = n * 32 + ((((j >> 2) ^ (n & 7)) << 2) | (j & 3));
        ((unsigned*)(smem + OFF_W2HI))[widx] = g_W2hi[i];
        ((unsigned*)(smem + OFF_W2LO))[widx] = g_W2lo[i];
    }
    if (tid < 32) {
        float4 u = g_w1pack[2*tid], v = g_w1pack[2*tid+1];
        s_l1w[2*tid]   = make_float4(u.x, v.x, u.y, v.y);
        s_l1w[2*tid+1] = make_float4(u.z, v.z, u.w, v.w);
        float4 a = g_k1pack[2*tid], b = g_k1pack[2*tid+1];
        s_l1k[2*tid]   = make_float4(a.x, b.x, a.y, b.y);
        s_l1k[2*tid+1] = make_float4(a.z, b.z, a.w, b.w);
    }
    __syncthreads();

    const uint32_t ub = smem_u32(smem);
    const uint32_t aoff = (uint32_t)((lane & 15) * 144 + ((lane >> 4) << 4));
    const uint32_t gg = (uint32_t)(lane >> 3), rr = (uint32_t)(lane & 7);
    const uint32_t rbl = ((gg >> 1) << 3) + rr;   // B n-row within 16-tile
    const uint32_t c0 = (gg & 1);                 // B k-chunk lsb
    const uint32_t Ahi = ub + OFF_H1 + wid * H1_WARP + aoff;
    const uint32_t Alo = Ahi + 4608;
    const uint32_t BhiBase = ub + OFF_W2HI + rbl * 128;
    const uint32_t BloBase = ub + OFF_W2LO + rbl * 128;
    char* h1hi_row = smem + OFF_H1 + wid * H1_WARP + lane * 144;
    char* h1lo_row = h1hi_row + 4608;

    for (int p = blockIdx.x * 4 + wid; p < P; p += gridDim.x * 4) {
        // ---- pillar meta (uniform loads) + point ----
        int np; long long rw, cl;
        if (is64) {
            np = (int)((const long long*)npts_raw)[p];
            rw = ((const long long*)coords_raw)[2 * p];
            cl = ((const long long*)coords_raw)[2 * p + 1];
        } else {
            np = ((const int*)npts_raw)[p];
            rw = (long long)((const int*)coords_raw)[2 * p];
            cl = (long long)((const int*)coords_raw)[2 * p + 1];
        }
        const float xc = ((float)cl + 0.5f) * RESV + XMINV;
        const float yc = ((float)rw + 0.5f) * RESV + YMINV;
        float4 pt = pillars[(size_t)p * 32 + lane];
        float zs = (lane < np) ? pt.z : 0.f;
#pragma unroll
        for (int o = 16; o; o >>= 1) zs += __shfl_xor_sync(0xffffffffu, zs, o);
        const float zm = zs / fmaxf((float)np, 1.f);

        // ---- per-(pillar,channel-pair) constants: lane t -> channels 2t,2t+1 ----
        {
            float4 ck = s_l1k[2 * lane];
            float4 dk = s_l1k[2 * lane + 1];
            float kc0 = ck.x - xc * ck.z - yc * dk.x - zm * dk.z;
            float kc1 = ck.y - xc * ck.w - yc * dk.y - zm * dk.w;
            *(float2*)(s_kc + (wid << 6) + 2 * lane) = make_float2(kc0, kc1);
        }
        __syncwarp();

        // ---- layer 1: lane = point row; split-bf16 rows to smem ----
        {
            const u64 xx = pack2(pt.x, pt.x), yy = pack2(pt.y, pt.y);
            const u64 zz = pack2(pt.z, pt.z), rr2 = pack2(pt.w, pt.w);
            const float* kcp = s_kc + (wid << 6);
            uint4 bh4, bl4;
#pragma unroll
            for (int j = 0; j < 32; j++) {
                ulonglong2 wab = *(const ulonglong2*)(s_l1w + 2 * j);
                ulonglong2 wcd = *(const ulonglong2*)(s_l1w + 2 * j + 1);
                u64 hp = *(const u64*)(kcp + 2 * j);
                fma2(hp, xx, wab.x); fma2(hp, yy, wab.y);
                fma2(hp, zz, wcd.x); fma2(hp, rr2, wcd.y);
                float h0, h1;
                asm("mov.b64 {%0,%1}, %2;" : "=f"(h0), "=f"(h1) : "l"(hp));
                h0 = fmaxf(h0, 0.f); h1 = fmaxf(h1, 0.f);
                unsigned hw, lw;
                asm("cvt.rn.bf16x2.f32 %0, %1, %2;" : "=r"(hw) : "f"(h1), "f"(h0));
                float e0 = h0 - __uint_as_float(hw << 16);
                float e1 = h1 - __uint_as_float(hw & 0xFFFF0000u);
                asm("cvt.rn.bf16x2.f32 %0, %1, %2;" : "=r"(lw) : "f"(e1), "f"(e0));
                (&bh4.x)[j & 3] = hw;
                (&bl4.x)[j & 3] = lw;
                if ((j & 3) == 3) {
                    *(uint4*)(h1hi_row + (j >> 2) * 16) = bh4;
                    *(uint4*)(h1lo_row + (j >> 2) * 16) = bl4;
                }
            }
        }
        __syncwarp();

        // ---- layer 2: HMMA, 3 split products; n in two halves of 32 channels ----
        const int rbase = lane >> 2;
#pragma unroll
        for (int h = 0; h < 2; h++) {
            float C[2][4][4];
#pragma unroll
            for (int mt = 0; mt < 2; mt++)
#pragma unroll
                for (int nt = 0; nt < 4; nt++)
#pragma unroll
                    for (int i = 0; i < 4; i++) C[mt][nt][i] = 0.f;

            const uint32_t bh0 = BhiBase + (uint32_t)h * 4096u;
            const uint32_t bl0 = BloBase + (uint32_t)h * 4096u;
#pragma unroll
            for (int ks = 0; ks < 4; ks++) {
                unsigned AH[2][4], AL[2][4], BH[2][4], BL[2][4];
                ldm4(AH[0], Ahi + ks * 32);
                ldm4(AH[1], Ahi + 2304 + ks * 32);
                ldm4(AL[0], Alo + ks * 32);
                ldm4(AL[1], Alo + 2304 + ks * 32);
                const uint32_t xorc = ((((uint32_t)ks * 2u + c0) ^ rr) << 4);
                ldm4(BH[0], bh0 + xorc);
                ldm4(BH[1], bh0 + 2048 + xorc);
                ldm4(BL[0], bl0 + xorc);
                ldm4(BL[1], bl0 + 2048 + xorc);
#pragma unroll
                for (int mt = 0; mt < 2; mt++)
#pragma unroll
                    for (int nt = 0; nt < 4; nt++) {
                        const unsigned* bhp = &BH[nt >> 1][(nt & 1) * 2];
                        const unsigned* blp = &BL[nt >> 1][(nt & 1) * 2];
                        mma_bf16(C[mt][nt], AH[mt], bhp[0], bhp[1]);
                        mma_bf16(C[mt][nt], AH[mt], blp[0], blp[1]);
                        mma_bf16(C[mt][nt], AL[mt], bhp[0], bhp[1]);
                    }
            }

            // ---- epilogue: masked max over points, butterfly, bias+relu ----
            const bool v0 = (rbase < np), v1 = (rbase + 8 < np);
            const bool v2 = (rbase + 16 < np), v3 = (rbase + 24 < np);
#pragma unroll
            for (int nt = 0; nt < 4; nt++) {
                float e = NEGV, o = NEGV;
                if (v0) { e = fmaxf(e, C[0][nt][0]); o = fmaxf(o, C[0][nt][1]); }
                if (v1) { e = fmaxf(e, C[0][nt][2]); o = fmaxf(o, C[0][nt][3]); }
                if (v2) { e = fmaxf(e, C[1][nt][0]); o = fmaxf(o, C[1][nt][1]); }
                if (v3) { e = fmaxf(e, C[1][nt][2]); o = fmaxf(o, C[1][nt][3]); }
#pragma unroll
                for (int off = 4; off <= 16; off <<= 1) {
                    e = fmaxf(e, __shfl_xor_sync(0xffffffffu, e, off));
                    o = fmaxf(o, __shfl_xor_sync(0xffffffffu, o, off));
                }
                if (lane < 4) {
                    int c = (h * 4 + nt) * 8 + 2 * lane;
                    float r0 = (np > 0) ? fmaxf(e + g_b2f[c], 0.f) : NEGV;
                    float r1 = (np > 0) ? fmaxf(o + g_b2f[c + 1], 0.f) : NEGV;
                    out[(size_t)p * 64 + c] = r0;
                    out[(size_t)p * 64 + c + 1] = r1;
                }
            }
        }
        __syncwarp();  // protect h1/kc smem reuse across loop iterations
    }
}

extern "C" void kernel_launch(void* const* d_in, const int* in_sizes, int n_in,
                              void* d_out, int out_size) {
    const float* pillars = (const float*)d_in[0];
    const void*  coords  = d_in[1];
    const void*  npts    = d_in[2];
    const float* W1 = (const float*)d_in[3];
    const float* b1 = (const float*)d_in[4];
    const float* g1 = (const float*)d_in[5];
    const float* be1 = (const float*)d_in[6];
    const float* m1 = (const float*)d_in[7];
    const float* v1 = (const float*)d_in[8];
    const float* W2 = (const float*)d_in[9];
    const float* b2 = (const float*)d_in[10];
    const float* g2 = (const float*)d_in[11];
    const float* be2 = (const float*)d_in[12];
    const float* m2 = (const float*)d_in[13];
    const float* v2 = (const float*)d_in[14];

    int P = in_sizes[0] / 128;
    int n_words = 2 * P < 4096 ? 2 * P : 4096;

    cudaFuncSetAttribute(pfn_main, cudaFuncAttributeMaxDynamicSharedMemorySize, SMEM_BYTES);

    prep_kernel<<<1, 64>>>(W1, b1, g1, be1, m1, v1, W2, b2, g2, be2, m2, v2,
                           (const unsigned*)coords, n_words);

    int grid = 4 * 152;
    int need = (P + 3) / 4;
    if (grid > need) grid = need;
    if (grid < 1) grid = 1;
    pfn_main<<<grid, 128, SMEM_BYTES>>>((const float4*)pillars, coords, npts,
                                        (float*)d_out, P);
}

// round 8
// speedup vs baseline: 3.2057x; 1.5088x over previous
#include <cuda_runtime.h>
#include <cuda_fp16.h>
#include <cstdint>

typedef unsigned long long u64;

#define RESV 0.16f
#define XMINV (-51.2f)
#define YMINV (-51.2f)
#define EPSV 1e-5f
#define NEGV (-1.0e9f)

// ---------------- folded weights ----------------
__device__ float4 g_w1pack[64];   // {Wx,Wy,Wz,Wr}*a1 per channel
__device__ float4 g_k1pack[64];   // {b1f, Wxc, Wyc, Wzm}
__device__ float  g_b2f[64];
__device__ unsigned g_W2h[2048];  // W2^T row c (n), k-major fp16x2 words
__device__ int g_is64;

__global__ void prep_kernel(const float* __restrict__ W1, const float* __restrict__ b1,
                            const float* __restrict__ g1, const float* __restrict__ beta1,
                            const float* __restrict__ m1, const float* __restrict__ v1,
                            const float* __restrict__ W2, const float* __restrict__ b2,
                            const float* __restrict__ g2, const float* __restrict__ beta2,
                            const float* __restrict__ m2, const float* __restrict__ v2,
                            const unsigned* __restrict__ coords_raw, int n_words) {
    int c = threadIdx.x;  // 0..63
    if (c == 0) g_is64 = 1;
    __syncthreads();
    int nz = 0;
    for (int i = 2 * c + 1; i < n_words; i += 128) nz |= (coords_raw[i] != 0u);
    if (nz) g_is64 = 0;

    float a1 = g1[c] * rsqrtf(v1[c] + EPSV);
    float w0 = W1[0*64+c], w1 = W1[1*64+c], w2v = W1[2*64+c];
    float w3 = W1[3*64+c], w4 = W1[4*64+c], w5 = W1[5*64+c];
    float w6 = W1[6*64+c], w7 = W1[7*64+c], w8 = W1[8*64+c];
    g_w1pack[c] = make_float4((w0+w4+w7)*a1, (w1+w5+w8)*a1, (w2v+w6)*a1, w3*a1);
    g_k1pack[c] = make_float4((b1[c]-m1[c])*a1 + beta1[c], (w4+w7)*a1, (w5+w8)*a1, w6*a1);

    float a2 = g2[c] * rsqrtf(v2[c] + EPSV);
    g_b2f[c] = (b2[c] - m2[c]) * a2 + beta2[c];
    for (int j = 0; j < 32; j++) {
        float v0  = W2[(2*j)   * 64 + c] * a2;
        float v1b = W2[(2*j+1) * 64 + c] * a2;
        unsigned hw;
        asm("cvt.rn.f16x2.f32 %0, %1, %2;" : "=r"(hw) : "f"(v1b), "f"(v0));
        g_W2h[c * 32 + j] = hw;  // low half = k=2j, high = k=2j+1
    }
}

// ---------------- helpers ----------------
__device__ __forceinline__ uint32_t smem_u32(const void* p) {
    uint32_t a;
    asm("{ .reg .u64 t; cvta.to.shared.u64 t, %1; cvt.u32.u64 %0, t; }" : "=r"(a) : "l"(p));
    return a;
}
__device__ __forceinline__ void fma2(u64& d, u64 a, u64 b) {
    asm("fma.rn.f32x2 %0, %1, %2, %0;" : "+l"(d) : "l"(a), "l"(b));
}
__device__ __forceinline__ u64 pack2(float lo, float hi) {
    u64 r;
    asm("mov.b64 %0, {%1, %2};" : "=l"(r) : "f"(lo), "f"(hi));
    return r;
}
__device__ __forceinline__ void ldm4(unsigned* r, uint32_t a) {
    asm volatile("ldmatrix.sync.aligned.m8n8.x4.shared.b16 {%0,%1,%2,%3}, [%4];"
        : "=r"(r[0]), "=r"(r[1]), "=r"(r[2]), "=r"(r[3]) : "r"(a));
}
__device__ __forceinline__ void mma_f16(float* c, const unsigned* a, unsigned b0, unsigned b1) {
    asm("mma.sync.aligned.m16n8k16.row.col.f32.f16.f16.f32 "
        "{%0,%1,%2,%3}, {%4,%5,%6,%7}, {%8,%9}, {%0,%1,%2,%3};"
        : "+f"(c[0]), "+f"(c[1]), "+f"(c[2]), "+f"(c[3])
        : "r"(a[0]), "r"(a[1]), "r"(a[2]), "r"(a[3]), "r"(b0), "r"(b1));
}

// ---------------- smem layout (29696B -> ~6 CTAs/SM, reg-bound) ----------------
#define OFF_L1W   0        // float4[64]: pairs {wx01,wy01},{wz01,wr01}
#define OFF_L1K   1024     // float4[64]: pairs {b1f01,wxc01},{wyc01,wzm01}
#define OFF_KC    2048     // float[4*64]
#define OFF_W2H   3072     // 64 rows x 128B, XOR-swizzled chunks
#define OFF_H1    11264    // 4 warps x (32 rows x 144B)
#define H1_WARP   4608
#define SMEM_BYTES 29696

__global__ void __launch_bounds__(128, 6)
pfn_main(const float4* __restrict__ pillars,
         const void* __restrict__ coords_raw,
         const void* __restrict__ npts_raw,
         float* __restrict__ out, int P) {
    extern __shared__ char smem[];
    const int tid = threadIdx.x;
    const int wid = tid >> 5;
    const int lane = tid & 31;
    const int is64 = g_is64;

    float4* s_l1w = (float4*)(smem + OFF_L1W);
    float4* s_l1k = (float4*)(smem + OFF_L1K);
    float*  s_kc  = (float*)(smem + OFF_KC);

    // ---- stage weights to smem (once); W2 tile 128B-stride, chunk^(row&7) swizzle ----
    for (int i = tid; i < 2048; i += 128) {
        int n = i >> 5, j = i & 31;
        int widx = n * 32 + ((((j >> 2) ^ (n & 7)) << 2) | (j & 3));
        ((unsigned*)(smem + OFF_W2H))[widx] = g_W2h[i];
    }
    if (tid < 32) {
        float4 u = g_w1pack[2*tid], v = g_w1pack[2*tid+1];
        s_l1w[2*tid]   = make_float4(u.x, v.x, u.y, v.y);
        s_l1w[2*tid+1] = make_float4(u.z, v.z, u.w, v.w);
        float4 a = g_k1pack[2*tid], b = g_k1pack[2*tid+1];
        s_l1k[2*tid]   = make_float4(a.x, b.x, a.y, b.y);
        s_l1k[2*tid+1] = make_float4(a.z, b.z, a.w, b.w);
    }
    __syncthreads();

    const uint32_t ub = smem_u32(smem);
    const uint32_t aoff = (uint32_t)((lane & 15) * 144 + ((lane >> 4) << 4));
    const uint32_t gg = (uint32_t)(lane >> 3), rr = (uint32_t)(lane & 7);
    const uint32_t rbl = ((gg >> 1) << 3) + rr;   // B n-row within 16-tile
    const uint32_t c0 = (gg & 1);                 // B k-chunk lsb
    const uint32_t Ah = ub + OFF_H1 + wid * H1_WARP + aoff;
    const uint32_t BBase = ub + OFF_W2H + rbl * 128;
    char* h1_row = smem + OFF_H1 + wid * H1_WARP + lane * 144;

    for (int p = blockIdx.x * 4 + wid; p < P; p += gridDim.x * 4) {
        // ---- pillar meta (uniform loads) + point ----
        int np; long long rw, cl;
        if (is64) {
            np = (int)((const long long*)npts_raw)[p];
            rw = ((const long long*)coords_raw)[2 * p];
            cl = ((const long long*)coords_raw)[2 * p + 1];
        } else {
            np = ((const int*)npts_raw)[p];
            rw = (long long)((const int*)coords_raw)[2 * p];
            cl = (long long)((const int*)coords_raw)[2 * p + 1];
        }
        const float xc = ((float)cl + 0.5f) * RESV + XMINV;
        const float yc = ((float)rw + 0.5f) * RESV + YMINV;
        float4 pt = pillars[(size_t)p * 32 + lane];
        float zs = (lane < np) ? pt.z : 0.f;
#pragma unroll
        for (int o = 16; o; o >>= 1) zs += __shfl_xor_sync(0xffffffffu, zs, o);
        const float zm = zs / fmaxf((float)np, 1.f);

        // ---- per-(pillar,channel-pair) constants: lane t -> channels 2t,2t+1 ----
        {
            float4 ck = s_l1k[2 * lane];
            float4 dk = s_l1k[2 * lane + 1];
            float kc0 = ck.x - xc * ck.z - yc * dk.x - zm * dk.z;
            float kc1 = ck.y - xc * ck.w - yc * dk.y - zm * dk.w;
            *(float2*)(s_kc + (wid << 6) + 2 * lane) = make_float2(kc0, kc1);
        }
        __syncwarp();

        // ---- layer 1: lane = point row; fp16 rows to smem ----
        {
            const u64 xx = pack2(pt.x, pt.x), yy = pack2(pt.y, pt.y);
            const u64 zz = pack2(pt.z, pt.z), rr2 = pack2(pt.w, pt.w);
            const float* kcp = s_kc + (wid << 6);
            uint4 bh4;
#pragma unroll
            for (int j = 0; j < 32; j++) {
                ulonglong2 wab = *(const ulonglong2*)(s_l1w + 2 * j);
                ulonglong2 wcd = *(const ulonglong2*)(s_l1w + 2 * j + 1);
                u64 hp = *(const u64*)(kcp + 2 * j);
                fma2(hp, xx, wab.x); fma2(hp, yy, wab.y);
                fma2(hp, zz, wcd.x); fma2(hp, rr2, wcd.y);
                float h0, h1;
                asm("mov.b64 {%0,%1}, %2;" : "=f"(h0), "=f"(h1) : "l"(hp));
                h0 = fmaxf(h0, 0.f); h1 = fmaxf(h1, 0.f);
                unsigned hw;
                asm("cvt.rn.f16x2.f32 %0, %1, %2;" : "=r"(hw) : "f"(h1), "f"(h0));
                (&bh4.x)[j & 3] = hw;
                if ((j & 3) == 3)
                    *(uint4*)(h1_row + (j >> 2) * 16) = bh4;
            }
        }
        __syncwarp();

        // ---- layer 2: single-product fp16 HMMA; n in two halves of 32 channels ----
        const int rbase = lane >> 2;
#pragma unroll
        for (int h = 0; h < 2; h++) {
            float C[2][4][4];
#pragma unroll
            for (int mt = 0; mt < 2; mt++)
#pragma unroll
                for (int nt = 0; nt < 4; nt++)
#pragma unroll
                    for (int i = 0; i < 4; i++) C[mt][nt][i] = 0.f;

            const uint32_t b0b = BBase + (uint32_t)h * 4096u;
#pragma unroll
            for (int ks = 0; ks < 4; ks++) {
                unsigned A[2][4], B[2][4];
                ldm4(A[0], Ah + ks * 32);
                ldm4(A[1], Ah + 2304 + ks * 32);
                const uint32_t xorc = ((((uint32_t)ks * 2u + c0) ^ rr) << 4);
                ldm4(B[0], b0b + xorc);
                ldm4(B[1], b0b + 2048 + xorc);
#pragma unroll
                for (int mt = 0; mt < 2; mt++)
#pragma unroll
                    for (int nt = 0; nt < 4; nt++) {
                        const unsigned* bp = &B[nt >> 1][(nt & 1) * 2];
                        mma_f16(C[mt][nt], A[mt], bp[0], bp[1]);
                    }
            }

            // ---- epilogue: masked max over points, butterfly, bias+relu ----
            const bool v0 = (rbase < np), v1 = (rbase + 8 < np);
            const bool v2 = (rbase + 16 < np), v3 = (rbase + 24 < np);
#pragma unroll
            for (int nt = 0; nt < 4; nt++) {
                float e = NEGV, o = NEGV;
                if (v0) { e = fmaxf(e, C[0][nt][0]); o = fmaxf(o, C[0][nt][1]); }
                if (v1) { e = fmaxf(e, C[0][nt][2]); o = fmaxf(o, C[0][nt][3]); }
                if (v2) { e = fmaxf(e, C[1][nt][0]); o = fmaxf(o, C[1][nt][1]); }
                if (v3) { e = fmaxf(e, C[1][nt][2]); o = fmaxf(o, C[1][nt][3]); }
#pragma unroll
                for (int off = 4; off <= 16; off <<= 1) {
                    e = fmaxf(e, __shfl_xor_sync(0xffffffffu, e, off));
                    o = fmaxf(o, __shfl_xor_sync(0xffffffffu, o, off));
                }
                if (lane < 4) {
                    int c = (h * 4 + nt) * 8 + 2 * lane;
                    float r0 = (np > 0) ? fmaxf(e + g_b2f[c], 0.f) : NEGV;
                    float r1 = (np > 0) ? fmaxf(o + g_b2f[c + 1], 0.f) : NEGV;
                    out[(size_t)p * 64 + c] = r0;
                    out[(size_t)p * 64 + c + 1] = r1;
                }
            }
        }
        __syncwarp();  // protect h1/kc smem reuse across loop iterations
    }
}

extern "C" void kernel_launch(void* const* d_in, const int* in_sizes, int n_in,
                              void* d_out, int out_size) {
    const float* pillars = (const float*)d_in[0];
    const void*  coords  = d_in[1];
    const void*  npts    = d_in[2];
    const float* W1 = (const float*)d_in[3];
    const float* b1 = (const float*)d_in[4];
    const float* g1 = (const float*)d_in[5];
    const float* be1 = (const float*)d_in[6];
    const float* m1 = (const float*)d_in[7];
    const float* v1 = (const float*)d_in[8];
    const float* W2 = (const float*)d_in[9];
    const float* b2 = (const float*)d_in[10];
    const float* g2 = (const float*)d_in[11];
    const float* be2 = (const float*)d_in[12];
    const float* m2 = (const float*)d_in[13];
    const float* v2 = (const float*)d_in[14];

    int P = in_sizes[0] / 128;
    int n_words = 2 * P < 4096 ? 2 * P : 4096;

    cudaFuncSetAttribute(pfn_main, cudaFuncAttributeMaxDynamicSharedMemorySize, SMEM_BYTES);

    prep_kernel<<<1, 64>>>(W1, b1, g1, be1, m1, v1, W2, b2, g2, be2, m2, v2,
                           (const unsigned*)coords, n_words);

    int grid = 6 * 152;
    int need = (P + 3) / 4;
    if (grid > need) grid = need;
    if (grid < 1) grid = 1;
    pfn_main<<<grid, 128, SMEM_BYTES>>>((const float4*)pillars, coords, npts,
                                        (float*)d_out, P);
}

// round 9
// speedup vs baseline: 4.2813x; 1.3355x over previous
#include <cuda_runtime.h>
#include <cuda_fp16.h>
#include <cstdint>

#define RESV 0.16f
#define XMINV (-51.2f)
#define YMINV (-51.2f)
#define EPSV 1e-5f
#define NEGV (-1.0e9f)

// ---------------- folded weights + fragment tables ----------------
__device__ float4 g_w1pack[64];    // {Wx,Wy,Wz,Wr}*a1 per channel
__device__ float4 g_k1pack[64];    // {b1f, Wxc, Wyc, Wzm}
__device__ float2 g_b2p[32];       // bias pairs (c=2i, 2i+1)
__device__ float  g_a2[64];
__device__ unsigned g_W1frag[256]; // [n-tile 0..7][lane] m16n8k8 B frags
__device__ uint2    g_W2frag[1024];// [(n-tile*4+k-tile)][lane] m16n8k16 B frags
__device__ int g_is64;

__device__ __forceinline__ unsigned pkf(float lo, float hi) {
    unsigned r;
    asm("cvt.rn.f16x2.f32 %0, %1, %2;" : "=r"(r) : "f"(hi), "f"(lo));
    return r;
}

__global__ void prep_kernel(const float* __restrict__ W1, const float* __restrict__ b1,
                            const float* __restrict__ g1, const float* __restrict__ beta1,
                            const float* __restrict__ m1, const float* __restrict__ v1,
                            const float* __restrict__ W2, const float* __restrict__ b2,
                            const float* __restrict__ g2, const float* __restrict__ beta2,
                            const float* __restrict__ m2, const float* __restrict__ v2,
                            const unsigned* __restrict__ coords_raw, int n_words) {
    int tid = threadIdx.x;  // 128 threads
    if (tid == 0) g_is64 = 1;
    __syncthreads();
    int nz = 0;
    for (int i = 2 * tid + 1; i < n_words; i += 256) nz |= (coords_raw[i] != 0u);
    if (nz) g_is64 = 0;

    if (tid < 64) {
        int c = tid;
        float a1 = g1[c] * rsqrtf(v1[c] + EPSV);
        float w0 = W1[0*64+c], w1 = W1[1*64+c], w2v = W1[2*64+c];
        float w3 = W1[3*64+c], w4 = W1[4*64+c], w5 = W1[5*64+c];
        float w6 = W1[6*64+c], w7 = W1[7*64+c], w8 = W1[8*64+c];
        g_w1pack[c] = make_float4((w0+w4+w7)*a1, (w1+w5+w8)*a1, (w2v+w6)*a1, w3*a1);
        g_k1pack[c] = make_float4((b1[c]-m1[c])*a1 + beta1[c], (w4+w7)*a1, (w5+w8)*a1, w6*a1);
        float a2 = g2[c] * rsqrtf(v2[c] + EPSV);
        g_a2[c] = a2;
        float bv = (b2[c] - m2[c]) * a2 + beta2[c];
        if (c & 1) ((float*)g_b2p)[c] = bv; else ((float*)g_b2p)[c] = bv;
    }
    __syncthreads();

    // W1 B-fragments (m16n8k8): n-tile t, lane l -> n=8t+l/4, k0=2(l%4)
    for (int idx = tid; idx < 256; idx += 128) {
        int t = idx >> 5, l = idx & 31;
        int n = 8 * t + (l >> 2), k0 = (l & 3) * 2;
        float4 wp = g_w1pack[n];
        float4 kp = g_k1pack[n];
        float row[8] = {wp.x, wp.y, wp.z, wp.w, -kp.y, -kp.z, -kp.w, kp.x};
        g_W1frag[idx] = pkf(row[k0], row[k0 + 1]);
    }
    // W2 B-fragments (m16n8k16): tile=(t2*4+ks), lane l -> n=8t2+l/4, j=l%4
    for (int idx = tid; idx < 1024; idx += 128) {
        int tile = idx >> 5, l = idx & 31;
        int t2 = tile >> 2, ks = tile & 3;
        int c = 8 * t2 + (l >> 2), j = l & 3;
        float a2v = g_a2[c];
        int k0 = 16 * ks + 2 * j;
        unsigned b0 = pkf(W2[k0 * 64 + c] * a2v,       W2[(k0 + 1) * 64 + c] * a2v);
        unsigned b1v = pkf(W2[(k0 + 8) * 64 + c] * a2v, W2[(k0 + 9) * 64 + c] * a2v);
        g_W2frag[idx] = make_uint2(b0, b1v);
    }
}

// ---------------- helpers ----------------
__device__ __forceinline__ uint32_t smem_u32(const void* p) {
    uint32_t a;
    asm("{ .reg .u64 t; cvta.to.shared.u64 t, %1; cvt.u32.u64 %0, t; }" : "=r"(a) : "l"(p));
    return a;
}
__device__ __forceinline__ void ldm4(unsigned* r, uint32_t a) {
    asm volatile("ldmatrix.sync.aligned.m8n8.x4.shared.b16 {%0,%1,%2,%3}, [%4];"
        : "=r"(r[0]), "=r"(r[1]), "=r"(r[2]), "=r"(r[3]) : "r"(a));
}
__device__ __forceinline__ void mma_k8(float* c, const unsigned* a, unsigned b0) {
    asm("mma.sync.aligned.m16n8k8.row.col.f32.f16.f16.f32 "
        "{%0,%1,%2,%3}, {%4,%5}, {%6}, {%0,%1,%2,%3};"
        : "+f"(c[0]), "+f"(c[1]), "+f"(c[2]), "+f"(c[3])
        : "r"(a[0]), "r"(a[1]), "r"(b0));
}
__device__ __forceinline__ void mma_f16(float* c, const unsigned* a, unsigned b0, unsigned b1) {
    asm("mma.sync.aligned.m16n8k16.row.col.f32.f16.f16.f32 "
        "{%0,%1,%2,%3}, {%4,%5,%6,%7}, {%8,%9}, {%0,%1,%2,%3};"
        : "+f"(c[0]), "+f"(c[1]), "+f"(c[2]), "+f"(c[3])
        : "r"(a[0]), "r"(a[1]), "r"(a[2]), "r"(a[3]), "r"(b0), "r"(b1));
}

__global__ void __launch_bounds__(128, 3)
pfn_main(const float4* __restrict__ pillars,
         const void* __restrict__ coords_raw,
         const void* __restrict__ npts_raw,
         float* __restrict__ out, int P) {
    __shared__ uint4 s_feat[128];  // 4 warps x 32 rows x 16B
    const int tid = threadIdx.x;
    const int wid = tid >> 5;
    const int lane = tid & 31;
    const int is64 = g_is64;

    // persistent weight fragments in registers
    unsigned W1B[8];
#pragma unroll
    for (int t = 0; t < 8; t++) W1B[t] = g_W1frag[t * 32 + lane];
    uint2 W2B[32];
#pragma unroll
    for (int i = 0; i < 32; i++) W2B[i] = g_W2frag[i * 32 + lane];

    const uint32_t featAddr = smem_u32(s_feat + (wid << 5)) + (uint32_t)lane * 16u;
    uint4* myfeat = s_feat + (wid << 5) + lane;
    const int rbase = lane >> 2;

    for (int p = blockIdx.x * 4 + wid; p < P; p += gridDim.x * 4) {
        // ---- pillar meta + point ----
        int np; long long rw, cl;
        if (is64) {
            np = (int)((const long long*)npts_raw)[p];
            rw = ((const long long*)coords_raw)[2 * p];
            cl = ((const long long*)coords_raw)[2 * p + 1];
        } else {
            np = ((const int*)npts_raw)[p];
            rw = (long long)((const int*)coords_raw)[2 * p];
            cl = (long long)((const int*)coords_raw)[2 * p + 1];
        }
        const float xc = ((float)cl + 0.5f) * RESV + XMINV;
        const float yc = ((float)rw + 0.5f) * RESV + YMINV;
        float4 pt = pillars[(size_t)p * 32 + lane];
        float zs = (lane < np) ? pt.z : 0.f;
#pragma unroll
        for (int o = 16; o; o >>= 1) zs += __shfl_xor_sync(0xffffffffu, zs, o);
        const float zm = zs / fmaxf((float)np, 1.f);

        // ---- feat row (fp16): [x,y,z,r,xc,yc,zm,1] ----
        *myfeat = make_uint4(pkf(pt.x, pt.y), pkf(pt.z, pt.w),
                             pkf(xc, yc), pkf(zm, 1.0f));
        __syncwarp();
        unsigned A1[4];
        ldm4(A1, featAddr);

        // ---- layer 1 via m16n8k8; C1 -> relu -> layer2 A fragments ----
        unsigned A2[2][4][4];
#pragma unroll
        for (int hh = 0; hh < 2; hh++) {
            float C1[2][4][4];
#pragma unroll
            for (int mt = 0; mt < 2; mt++)
#pragma unroll
                for (int nt = 0; nt < 4; nt++)
#pragma unroll
                    for (int i = 0; i < 4; i++) C1[mt][nt][i] = 0.f;
#pragma unroll
            for (int mt = 0; mt < 2; mt++)
#pragma unroll
                for (int nt = 0; nt < 4; nt++)
                    mma_k8(C1[mt][nt], &A1[mt * 2], W1B[hh * 4 + nt]);
#pragma unroll
            for (int mt = 0; mt < 2; mt++)
#pragma unroll
                for (int nt = 0; nt < 4; nt++) {
                    int s = hh * 2 + (nt >> 1), sel = nt & 1;
                    A2[mt][s][2 * sel] =
                        pkf(fmaxf(C1[mt][nt][0], 0.f), fmaxf(C1[mt][nt][1], 0.f));
                    A2[mt][s][2 * sel + 1] =
                        pkf(fmaxf(C1[mt][nt][2], 0.f), fmaxf(C1[mt][nt][3], 0.f));
                }
        }

        // ---- layer 2 via m16n8k16 + epilogue ----
        const bool v0 = (rbase < np), v1 = (rbase + 8 < np);
        const bool v2 = (rbase + 16 < np), v3 = (rbase + 24 < np);
#pragma unroll
        for (int hh2 = 0; hh2 < 2; hh2++) {
            float C2[2][4][4];
#pragma unroll
            for (int mt = 0; mt < 2; mt++)
#pragma unroll
                for (int nt = 0; nt < 4; nt++)
#pragma unroll
                    for (int i = 0; i < 4; i++) C2[mt][nt][i] = 0.f;
#pragma unroll
            for (int ks = 0; ks < 4; ks++)
#pragma unroll
                for (int mt = 0; mt < 2; mt++)
#pragma unroll
                    for (int nt = 0; nt < 4; nt++) {
                        uint2 b = W2B[(hh2 * 4 + nt) * 4 + ks];
                        mma_f16(C2[mt][nt], A2[mt][ks], b.x, b.y);
                    }
            // masked max over points, butterfly, bias+relu
#pragma unroll
            for (int nt = 0; nt < 4; nt++) {
                float e = NEGV, o = NEGV;
                if (v0) { e = fmaxf(e, C2[0][nt][0]); o = fmaxf(o, C2[0][nt][1]); }
                if (v1) { e = fmaxf(e, C2[0][nt][2]); o = fmaxf(o, C2[0][nt][3]); }
                if (v2) { e = fmaxf(e, C2[1][nt][0]); o = fmaxf(o, C2[1][nt][1]); }
                if (v3) { e = fmaxf(e, C2[1][nt][2]); o = fmaxf(o, C2[1][nt][3]); }
#pragma unroll
                for (int off = 4; off <= 16; off <<= 1) {
                    e = fmaxf(e, __shfl_xor_sync(0xffffffffu, e, off));
                    o = fmaxf(o, __shfl_xor_sync(0xffffffffu, o, off));
                }
                if (lane < 4) {
                    int t2 = hh2 * 4 + nt;
                    float2 bv = g_b2p[t2 * 4 + lane];
                    float2 res;
                    res.x = (np > 0) ? fmaxf(e + bv.x, 0.f) : NEGV;
                    res.y = (np > 0) ? fmaxf(o + bv.y, 0.f) : NEGV;
                    *(float2*)(out + (size_t)p * 64 + t2 * 8 + 2 * lane) = res;
                }
            }
        }
        __syncwarp();  // protect s_feat reuse across iterations
    }
}

extern "C" void kernel_launch(void* const* d_in, const int* in_sizes, int n_in,
                              void* d_out, int out_size) {
    const float* pillars = (const float*)d_in[0];
    const void*  coords  = d_in[1];
    const void*  npts    = d_in[2];
    const float* W1 = (const float*)d_in[3];
    const float* b1 = (const float*)d_in[4];
    const float* g1 = (const float*)d_in[5];
    const float* be1 = (const float*)d_in[6];
    const float* m1 = (const float*)d_in[7];
    const float* v1 = (const float*)d_in[8];
    const float* W2 = (const float*)d_in[9];
    const float* b2 = (const float*)d_in[10];
    const float* g2 = (const float*)d_in[11];
    const float* be2 = (const float*)d_in[12];
    const float* m2 = (const float*)d_in[13];
    const float* v2 = (const float*)d_in[14];

    int P = in_sizes[0] / 128;
    int n_words = 2 * P < 4096 ? 2 * P : 4096;

    prep_kernel<<<1, 128>>>(W1, b1, g1, be1, m1, v1, W2, b2, g2, be2, m2, v2,
                            (const unsigned*)coords, n_words);

    int grid = 3 * 152;
    int need = (P + 3) / 4;
    if (grid > need) grid = need;
    if (grid < 1) grid = 1;
    pfn_main<<<grid, 128>>>((const float4*)pillars, coords, npts, (float*)d_out, P);
}

// round 10
// speedup vs baseline: 4.8404x; 1.1306x over previous
#include <cuda_runtime.h>
#include <cuda_fp16.h>
#include <cstdint>

#define RESV 0.16f
#define XMINV (-51.2f)
#define YMINV (-51.2f)
#define EPSV 1e-5f
#define NEGV (-1.0e9f)
#define NEGH2 0xFBFFFBFFu   // fp16x2 {-65504,-65504}

// ---------------- folded weights + fragment tables ----------------
__device__ float4 g_w1pack[64];    // {Wx,Wy,Wz,Wr}*a1 per channel
__device__ float4 g_k1pack[64];    // {b1f, Wxc, Wyc, Wzm}
__device__ float2 g_b2p[32];       // bias pairs (c=2i, 2i+1)
__device__ float  g_a2[64];
__device__ unsigned g_W1frag[256]; // [n-tile 0..7][lane] m16n8k8 B frags
__device__ uint2    g_W2frag[1024];// [(n-tile*4+k-tile)][lane] m16n8k16 B frags
__device__ int g_is64;

__device__ __forceinline__ unsigned pkf(float lo, float hi) {
    unsigned r;
    asm("cvt.rn.f16x2.f32 %0, %1, %2;" : "=r"(r) : "f"(hi), "f"(lo));
    return r;
}

__global__ void prep_kernel(const float* __restrict__ W1, const float* __restrict__ b1,
                            const float* __restrict__ g1, const float* __restrict__ beta1,
                            const float* __restrict__ m1, const float* __restrict__ v1,
                            const float* __restrict__ W2, const float* __restrict__ b2,
                            const float* __restrict__ g2, const float* __restrict__ beta2,
                            const float* __restrict__ m2, const float* __restrict__ v2,
                            const unsigned* __restrict__ coords_raw, int n_words) {
    int tid = threadIdx.x;  // 128 threads
    if (tid == 0) g_is64 = 1;
    __syncthreads();
    int nz = 0;
    for (int i = 2 * tid + 1; i < n_words; i += 256) nz |= (coords_raw[i] != 0u);
    if (nz) g_is64 = 0;

    if (tid < 64) {
        int c = tid;
        float a1 = g1[c] * rsqrtf(v1[c] + EPSV);
        float w0 = W1[0*64+c], w1 = W1[1*64+c], w2v = W1[2*64+c];
        float w3 = W1[3*64+c], w4 = W1[4*64+c], w5 = W1[5*64+c];
        float w6 = W1[6*64+c], w7 = W1[7*64+c], w8 = W1[8*64+c];
        g_w1pack[c] = make_float4((w0+w4+w7)*a1, (w1+w5+w8)*a1, (w2v+w6)*a1, w3*a1);
        g_k1pack[c] = make_float4((b1[c]-m1[c])*a1 + beta1[c], (w4+w7)*a1, (w5+w8)*a1, w6*a1);
        float a2 = g2[c] * rsqrtf(v2[c] + EPSV);
        g_a2[c] = a2;
        ((float*)g_b2p)[c] = (b2[c] - m2[c]) * a2 + beta2[c];
    }
    __syncthreads();

    // W1 B-fragments (m16n8k8): n-tile t, lane l -> n=8t+l/4, k0=2(l%4)
    for (int idx = tid; idx < 256; idx += 128) {
        int t = idx >> 5, l = idx & 31;
        int n = 8 * t + (l >> 2), k0 = (l & 3) * 2;
        float4 wp = g_w1pack[n];
        float4 kp = g_k1pack[n];
        float row[8] = {wp.x, wp.y, wp.z, wp.w, -kp.y, -kp.z, -kp.w, kp.x};
        g_W1frag[idx] = pkf(row[k0], row[k0 + 1]);
    }
    // W2 B-fragments (m16n8k16): tile=(t2*4+ks), lane l -> n=8t2+l/4, j=l%4
    for (int idx = tid; idx < 1024; idx += 128) {
        int tile = idx >> 5, l = idx & 31;
        int t2 = tile >> 2, ks = tile & 3;
        int c = 8 * t2 + (l >> 2), j = l & 3;
        float a2v = g_a2[c];
        int k0 = 16 * ks + 2 * j;
        unsigned b0 = pkf(W2[k0 * 64 + c] * a2v,        W2[(k0 + 1) * 64 + c] * a2v);
        unsigned b1v = pkf(W2[(k0 + 8) * 64 + c] * a2v, W2[(k0 + 9) * 64 + c] * a2v);
        g_W2frag[idx] = make_uint2(b0, b1v);
    }
}

// ---------------- helpers ----------------
__device__ __forceinline__ uint32_t smem_u32(const void* p) {
    uint32_t a;
    asm("{ .reg .u64 t; cvta.to.shared.u64 t, %1; cvt.u32.u64 %0, t; }" : "=r"(a) : "l"(p));
    return a;
}
__device__ __forceinline__ void ldm4(unsigned* r, uint32_t a) {
    asm volatile("ldmatrix.sync.aligned.m8n8.x4.shared.b16 {%0,%1,%2,%3}, [%4];"
        : "=r"(r[0]), "=r"(r[1]), "=r"(r[2]), "=r"(r[3]) : "r"(a));
}
// first-MMA variants: C operand = 0 (no accumulator init MOVs)
__device__ __forceinline__ void mma_k8_z(float* d, const unsigned* a, unsigned b0) {
    asm("mma.sync.aligned.m16n8k8.row.col.f32.f16.f16.f32 "
        "{%0,%1,%2,%3}, {%4,%5}, {%6}, {%7,%8,%9,%10};"
        : "=f"(d[0]), "=f"(d[1]), "=f"(d[2]), "=f"(d[3])
        : "r"(a[0]), "r"(a[1]), "r"(b0),
          "f"(0.f), "f"(0.f), "f"(0.f), "f"(0.f));
}
__device__ __forceinline__ void mma_f16_z(float* d, const unsigned* a, unsigned b0, unsigned b1) {
    asm("mma.sync.aligned.m16n8k16.row.col.f32.f16.f16.f32 "
        "{%0,%1,%2,%3}, {%4,%5,%6,%7}, {%8,%9}, {%10,%11,%12,%13};"
        : "=f"(d[0]), "=f"(d[1]), "=f"(d[2]), "=f"(d[3])
        : "r"(a[0]), "r"(a[1]), "r"(a[2]), "r"(a[3]), "r"(b0), "r"(b1),
          "f"(0.f), "f"(0.f), "f"(0.f), "f"(0.f));
}
__device__ __forceinline__ void mma_f16(float* c, const unsigned* a, unsigned b0, unsigned b1) {
    asm("mma.sync.aligned.m16n8k16.row.col.f32.f16.f16.f32 "
        "{%0,%1,%2,%3}, {%4,%5,%6,%7}, {%8,%9}, {%0,%1,%2,%3};"
        : "+f"(c[0]), "+f"(c[1]), "+f"(c[2]), "+f"(c[3])
        : "r"(a[0]), "r"(a[1]), "r"(a[2]), "r"(a[3]), "r"(b0), "r"(b1));
}
__device__ __forceinline__ unsigned hmax2(unsigned a, unsigned b) {
    unsigned r;
    asm("max.f16x2 %0, %1, %2;" : "=r"(r) : "r"(a), "r"(b));
    return r;
}

__device__ __forceinline__ void load_pillar(int p, int is64,
        const void* __restrict__ coords_raw, const void* __restrict__ npts_raw,
        const float4* __restrict__ pillars, int lane,
        int& np, float& xc, float& yc, float4& pt) {
    long long rw, cl;
    if (is64) {
        np = (int)((const long long*)npts_raw)[p];
        rw = ((const long long*)coords_raw)[2 * p];
        cl = ((const long long*)coords_raw)[2 * p + 1];
    } else {
        np = ((const int*)npts_raw)[p];
        rw = (long long)((const int*)coords_raw)[2 * p];
        cl = (long long)((const int*)coords_raw)[2 * p + 1];
    }
    xc = ((float)cl + 0.5f) * RESV + XMINV;
    yc = ((float)rw + 0.5f) * RESV + YMINV;
    pt = pillars[(size_t)p * 32 + lane];
}

__global__ void __launch_bounds__(128, 3)
pfn_main(const float4* __restrict__ pillars,
         const void* __restrict__ coords_raw,
         const void* __restrict__ npts_raw,
         float* __restrict__ out, int P) {
    __shared__ uint4 s_feat[128];   // 4 warps x 32 rows x 16B
    __shared__ float2 s_b2p[32];
    const int tid = threadIdx.x;
    const int wid = tid >> 5;
    const int lane = tid & 31;
    const int is64 = g_is64;

    if (tid < 32) s_b2p[tid] = g_b2p[tid];

    // persistent weight fragments in registers
    unsigned W1B[8];
#pragma unroll
    for (int t = 0; t < 8; t++) W1B[t] = g_W1frag[t * 32 + lane];
    uint2 W2B[32];
#pragma unroll
    for (int i = 0; i < 32; i++) W2B[i] = g_W2frag[i * 32 + lane];

    const uint32_t featAddr = smem_u32(s_feat + (wid << 5)) + (uint32_t)lane * 16u;
    uint4* myfeat = s_feat + (wid << 5) + lane;
    const int rbase = lane >> 2;
    const int stride = gridDim.x * 4;
    __syncthreads();  // s_b2p ready

    int p = blockIdx.x * 4 + wid;
    int np = 0; float xc = 0.f, yc = 0.f; float4 pt = make_float4(0.f, 0.f, 0.f, 0.f);
    if (p < P) load_pillar(p, is64, coords_raw, npts_raw, pillars, lane, np, xc, yc, pt);

    while (p < P) {
        // ---- capture current, issue prefetch for next ----
        const int cp = p, cnp = np;
        const float cxc = xc, cyc = yc;
        const float4 cpt = pt;
        p += stride;
        if (p < P) load_pillar(p, is64, coords_raw, npts_raw, pillars, lane, np, xc, yc, pt);

        // ---- zmean ----
        float zs = (lane < cnp) ? cpt.z : 0.f;
#pragma unroll
        for (int o = 16; o; o >>= 1) zs += __shfl_xor_sync(0xffffffffu, zs, o);
        const float zm = zs / fmaxf((float)cnp, 1.f);

        // ---- feat row (fp16): [x,y,z,r,xc,yc,zm,1] ----
        *myfeat = make_uint4(pkf(cpt.x, cpt.y), pkf(cpt.z, cpt.w),
                             pkf(cxc, cyc), pkf(zm, 1.0f));
        __syncwarp();
        unsigned A1[4];
        ldm4(A1, featAddr);
        __syncwarp();

        // ---- layer 1 via m16n8k8 (K=8, single MMA per chain, zero C) ----
        unsigned A2[2][4][4];
#pragma unroll
        for (int hh = 0; hh < 2; hh++)
#pragma unroll
            for (int mt = 0; mt < 2; mt++)
#pragma unroll
                for (int nt = 0; nt < 4; nt++) {
                    float C1[4];
                    mma_k8_z(C1, &A1[mt * 2], W1B[hh * 4 + nt]);
                    int s = hh * 2 + (nt >> 1), sel = nt & 1;
                    A2[mt][s][2 * sel] = pkf(fmaxf(C1[0], 0.f), fmaxf(C1[1], 0.f));
                    A2[mt][s][2 * sel + 1] = pkf(fmaxf(C1[2], 0.f), fmaxf(C1[3], 0.f));
                }

        // ---- layer 2 via m16n8k16 + packed-fp16 epilogue ----
        const bool v0 = (rbase < cnp), v1 = (rbase + 8 < cnp);
        const bool v2 = (rbase + 16 < cnp), v3 = (rbase + 24 < cnp);
#pragma unroll
        for (int hh2 = 0; hh2 < 2; hh2++) {
            float C2[2][4][4];
#pragma unroll
            for (int mt = 0; mt < 2; mt++)
#pragma unroll
                for (int nt = 0; nt < 4; nt++) {
                    uint2 b = W2B[(hh2 * 4 + nt) * 4];
                    mma_f16_z(C2[mt][nt], A2[mt][0], b.x, b.y);
                }
#pragma unroll
            for (int ks = 1; ks < 4; ks++)
#pragma unroll
                for (int mt = 0; mt < 2; mt++)
#pragma unroll
                    for (int nt = 0; nt < 4; nt++) {
                        uint2 b = W2B[(hh2 * 4 + nt) * 4 + ks];
                        mma_f16(C2[mt][nt], A2[mt][ks], b.x, b.y);
                    }
#pragma unroll
            for (int nt = 0; nt < 4; nt++) {
                unsigned m0 = pkf(C2[0][nt][0], C2[0][nt][1]);
                unsigned m1 = pkf(C2[0][nt][2], C2[0][nt][3]);
                unsigned m2v = pkf(C2[1][nt][0], C2[1][nt][1]);
                unsigned m3 = pkf(C2[1][nt][2], C2[1][nt][3]);
                unsigned best = NEGH2;
                if (v0) best = hmax2(best, m0);
                if (v1) best = hmax2(best, m1);
                if (v2) best = hmax2(best, m2v);
                if (v3) best = hmax2(best, m3);
#pragma unroll
                for (int off = 4; off <= 16; off <<= 1)
                    best = hmax2(best, __shfl_xor_sync(0xffffffffu, best, off));
                if (lane < 4) {
                    int t2 = hh2 * 4 + nt;
                    float2 bv = s_b2p[t2 * 4 + lane];
                    __half2 bh = *reinterpret_cast<__half2*>(&best);
                    float2 res;
                    res.x = (cnp > 0) ? fmaxf(__low2float(bh) + bv.x, 0.f) : NEGV;
                    res.y = (cnp > 0) ? fmaxf(__high2float(bh) + bv.y, 0.f) : NEGV;
                    *(float2*)(out + (size_t)cp * 64 + t2 * 8 + 2 * lane) = res;
                }
            }
        }
        __syncwarp();  // protect s_feat reuse across iterations
    }
}

extern "C" void kernel_launch(void* const* d_in, const int* in_sizes, int n_in,
                              void* d_out, int out_size) {
    const float* pillars = (const float*)d_in[0];
    const void*  coords  = d_in[1];
    const void*  npts    = d_in[2];
    const float* W1 = (const float*)d_in[3];
    const float* b1 = (const float*)d_in[4];
    const float* g1 = (const float*)d_in[5];
    const float* be1 = (const float*)d_in[6];
    const float* m1 = (const float*)d_in[7];
    const float* v1 = (const float*)d_in[8];
    const float* W2 = (const float*)d_in[9];
    const float* b2 = (const float*)d_in[10];
    const float* g2 = (const float*)d_in[11];
    const float* be2 = (const float*)d_in[12];
    const float* m2 = (const float*)d_in[13];
    const float* v2 = (const float*)d_in[14];

    int P = in_sizes[0] / 128;
    int n_words = 2 * P < 4096 ? 2 * P : 4096;

    prep_kernel<<<1, 128>>>(W1, b1, g1, be1, m1, v1, W2, b2, g2, be2, m2, v2,
                            (const unsigned*)coords, n_words);

    int grid = 3 * 152;
    int need = (P + 3) / 4;
    if (grid > need) grid = need;
    if (grid < 1) grid = 1;
    pfn_main<<<grid, 128>>>((const float4*)pillars, coords, npts, (float*)d_out, P);
}

// round 11
// speedup vs baseline: 5.1865x; 1.0715x over previous
#include <cuda_runtime.h>
#include <cuda_fp16.h>
#include <cstdint>

#define RESV 0.16f
#define XMINV (-51.2f)
#define YMINV (-51.2f)
#define EPSV 1e-5f
#define NEGV (-1.0e9f)
#define NEGH2 0xFBFFFBFFu   // fp16x2 {-65504,-65504}

// ---------------- folded weights + fragment tables ----------------
__device__ float4 g_w1pack[64];    // {Wx,Wy,Wz,Wr}*a1 per channel
__device__ float4 g_k1pack[64];    // {b1f, Wxc, Wyc, Wzm}
__device__ float2 g_b2p[32];       // bias pairs (c=2i, 2i+1)
__device__ float  g_a2[64];
__device__ unsigned g_W1frag[256]; // [n-tile 0..7][lane] m16n8k8 B frags
__device__ uint2    g_W2frag[1024];// [(n-tile*4+k-tile)][lane] m16n8k16 B frags
__device__ int g_is64;

__device__ __forceinline__ unsigned pkf(float lo, float hi) {
    unsigned r;
    asm("cvt.rn.f16x2.f32 %0, %1, %2;" : "=r"(r) : "f"(hi), "f"(lo));
    return r;
}

__global__ void prep_kernel(const float* __restrict__ W1, const float* __restrict__ b1,
                            const float* __restrict__ g1, const float* __restrict__ beta1,
                            const float* __restrict__ m1, const float* __restrict__ v1,
                            const float* __restrict__ W2, const float* __restrict__ b2,
                            const float* __restrict__ g2, const float* __restrict__ beta2,
                            const float* __restrict__ m2, const float* __restrict__ v2,
                            const unsigned* __restrict__ coords_raw, int n_words) {
    int tid = threadIdx.x;  // 128 threads
    if (tid == 0) g_is64 = 1;
    __syncthreads();
    int nz = 0;
    for (int i = 2 * tid + 1; i < n_words; i += 256) nz |= (coords_raw[i] != 0u);
    if (nz) g_is64 = 0;

    if (tid < 64) {
        int c = tid;
        float a1 = g1[c] * rsqrtf(v1[c] + EPSV);
        float w0 = W1[0*64+c], w1 = W1[1*64+c], w2v = W1[2*64+c];
        float w3 = W1[3*64+c], w4 = W1[4*64+c], w5 = W1[5*64+c];
        float w6 = W1[6*64+c], w7 = W1[7*64+c], w8 = W1[8*64+c];
        g_w1pack[c] = make_float4((w0+w4+w7)*a1, (w1+w5+w8)*a1, (w2v+w6)*a1, w3*a1);
        g_k1pack[c] = make_float4((b1[c]-m1[c])*a1 + beta1[c], (w4+w7)*a1, (w5+w8)*a1, w6*a1);
        float a2 = g2[c] * rsqrtf(v2[c] + EPSV);
        g_a2[c] = a2;
        ((float*)g_b2p)[c] = (b2[c] - m2[c]) * a2 + beta2[c];
    }
    __syncthreads();

    // W1 B-fragments (m16n8k8): n-tile t, lane l -> n=8t+l/4, k0=2(l%4)
    for (int idx = tid; idx < 256; idx += 128) {
        int t = idx >> 5, l = idx & 31;
        int n = 8 * t + (l >> 2), k0 = (l & 3) * 2;
        float4 wp = g_w1pack[n];
        float4 kp = g_k1pack[n];
        float row[8] = {wp.x, wp.y, wp.z, wp.w, -kp.y, -kp.z, -kp.w, kp.x};
        g_W1frag[idx] = pkf(row[k0], row[k0 + 1]);
    }
    // W2 B-fragments (m16n8k16): tile=(t2*4+ks), lane l -> n=8t2+l/4, j=l%4
    for (int idx = tid; idx < 1024; idx += 128) {
        int tile = idx >> 5, l = idx & 31;
        int t2 = tile >> 2, ks = tile & 3;
        int c = 8 * t2 + (l >> 2), j = l & 3;
        float a2v = g_a2[c];
        int k0 = 16 * ks + 2 * j;
        unsigned b0 = pkf(W2[k0 * 64 + c] * a2v,        W2[(k0 + 1) * 64 + c] * a2v);
        unsigned b1v = pkf(W2[(k0 + 8) * 64 + c] * a2v, W2[(k0 + 9) * 64 + c] * a2v);
        g_W2frag[idx] = make_uint2(b0, b1v);
    }
}

// ---------------- helpers ----------------
__device__ __forceinline__ uint32_t smem_u32(const void* p) {
    uint32_t a;
    asm("{ .reg .u64 t; cvta.to.shared.u64 t, %1; cvt.u32.u64 %0, t; }" : "=r"(a) : "l"(p));
    return a;
}
__device__ __forceinline__ void ldm4(unsigned* r, uint32_t a) {
    asm volatile("ldmatrix.sync.aligned.m8n8.x4.shared.b16 {%0,%1,%2,%3}, [%4];"
        : "=r"(r[0]), "=r"(r[1]), "=r"(r[2]), "=r"(r[3]) : "r"(a));
}
__device__ __forceinline__ void mma_k8_z(float* d, const unsigned* a, unsigned b0) {
    asm("mma.sync.aligned.m16n8k8.row.col.f32.f16.f16.f32 "
        "{%0,%1,%2,%3}, {%4,%5}, {%6}, {%7,%8,%9,%10};"
        : "=f"(d[0]), "=f"(d[1]), "=f"(d[2]), "=f"(d[3])
        : "r"(a[0]), "r"(a[1]), "r"(b0),
          "f"(0.f), "f"(0.f), "f"(0.f), "f"(0.f));
}
__device__ __forceinline__ void mma_f16_z(float* d, const unsigned* a, unsigned b0, unsigned b1) {
    asm("mma.sync.aligned.m16n8k16.row.col.f32.f16.f16.f32 "
        "{%0,%1,%2,%3}, {%4,%5,%6,%7}, {%8,%9}, {%10,%11,%12,%13};"
        : "=f"(d[0]), "=f"(d[1]), "=f"(d[2]), "=f"(d[3])
        : "r"(a[0]), "r"(a[1]), "r"(a[2]), "r"(a[3]), "r"(b0), "r"(b1),
          "f"(0.f), "f"(0.f), "f"(0.f), "f"(0.f));
}
__device__ __forceinline__ void mma_f16(float* c, const unsigned* a, unsigned b0, unsigned b1) {
    asm("mma.sync.aligned.m16n8k16.row.col.f32.f16.f16.f32 "
        "{%0,%1,%2,%3}, {%4,%5,%6,%7}, {%8,%9}, {%0,%1,%2,%3};"
        : "+f"(c[0]), "+f"(c[1]), "+f"(c[2]), "+f"(c[3])
        : "r"(a[0]), "r"(a[1]), "r"(a[2]), "r"(a[3]), "r"(b0), "r"(b1));
}
__device__ __forceinline__ unsigned hmax2(unsigned a, unsigned b) {
    unsigned r;
    asm("max.f16x2 %0, %1, %2;" : "=r"(r) : "r"(a), "r"(b));
    return r;
}

__device__ __forceinline__ void load_pillar(int p, int is64,
        const void* __restrict__ coords_raw, const void* __restrict__ npts_raw,
        const float4* __restrict__ pillars, int lane,
        int& np, float& xc, float& yc, float4& pt) {
    long long rw, cl;
    if (is64) {
        np = (int)((const long long*)npts_raw)[p];
        rw = ((const long long*)coords_raw)[2 * p];
        cl = ((const long long*)coords_raw)[2 * p + 1];
    } else {
        np = ((const int*)npts_raw)[p];
        rw = (long long)((const int*)coords_raw)[2 * p];
        cl = (long long)((const int*)coords_raw)[2 * p + 1];
    }
    xc = ((float)cl + 0.5f) * RESV + XMINV;
    yc = ((float)rw + 0.5f) * RESV + YMINV;
    pt = pillars[(size_t)p * 32 + lane];
}

__global__ void __launch_bounds__(128, 3)
pfn_main(const float4* __restrict__ pillars,
         const void* __restrict__ coords_raw,
         const void* __restrict__ npts_raw,
         float* __restrict__ out, int P) {
    __shared__ uint4 s_feat[128];   // 4 warps x 32 rows x 16B
    __shared__ float2 s_b2p[32];
    const int tid = threadIdx.x;
    const int wid = tid >> 5;
    const int lane = tid & 31;
    const int is64 = g_is64;

    if (tid < 32) s_b2p[tid] = g_b2p[tid];

    // persistent weight fragments in registers
    unsigned W1B[8];
#pragma unroll
    for (int t = 0; t < 8; t++) W1B[t] = g_W1frag[t * 32 + lane];
    uint2 W2B[32];
#pragma unroll
    for (int i = 0; i < 32; i++) W2B[i] = g_W2frag[i * 32 + lane];

    const uint32_t featAddr = smem_u32(s_feat + (wid << 5)) + (uint32_t)lane * 16u;
    uint4* myfeat = s_feat + (wid << 5) + lane;
    const int rbase = lane >> 2;
    const int stride = gridDim.x * 4;
    __syncthreads();  // s_b2p ready

    int p = blockIdx.x * 4 + wid;
    int np = 0; float xc = 0.f, yc = 0.f; float4 pt = make_float4(0.f, 0.f, 0.f, 0.f);
    if (p < P) load_pillar(p, is64, coords_raw, npts_raw, pillars, lane, np, xc, yc, pt);

    while (p < P) {
        // ---- capture current, issue prefetch for next ----
        const int cp = p, cnp = np;
        const float cxc = xc, cyc = yc;
        const float4 cpt = pt;
        p += stride;
        if (p < P) load_pillar(p, is64, coords_raw, npts_raw, pillars, lane, np, xc, yc, pt);

        // ---- empty pillar: output is all NEGV, skip all compute (warp-uniform) ----
        if (cnp == 0) {
            *(float2*)(out + (size_t)cp * 64 + 2 * lane) = make_float2(NEGV, NEGV);
            continue;
        }
        const bool big = (cnp > 16);  // warp-uniform: need rows 16..31?

        // ---- zmean ----
        float zs = (lane < cnp) ? cpt.z : 0.f;
#pragma unroll
        for (int o = 16; o; o >>= 1) zs += __shfl_xor_sync(0xffffffffu, zs, o);
        const float zm = zs / (float)cnp;

        // ---- feat row (fp16): [x,y,z,r,xc,yc,zm,1] ----
        *myfeat = make_uint4(pkf(cpt.x, cpt.y), pkf(cpt.z, cpt.w),
                             pkf(cxc, cyc), pkf(zm, 1.0f));
        __syncwarp();
        unsigned A1[4];
        ldm4(A1, featAddr);
        __syncwarp();

        // ---- layer 1 via m16n8k8; mt=1 only when rows 16..31 are live ----
        unsigned A2[2][4][4];
#pragma unroll
        for (int hh = 0; hh < 2; hh++)
#pragma unroll
            for (int nt = 0; nt < 4; nt++) {
                float C1[4];
                mma_k8_z(C1, &A1[0], W1B[hh * 4 + nt]);
                int s = hh * 2 + (nt >> 1), sel = nt & 1;
                A2[0][s][2 * sel] = pkf(fmaxf(C1[0], 0.f), fmaxf(C1[1], 0.f));
                A2[0][s][2 * sel + 1] = pkf(fmaxf(C1[2], 0.f), fmaxf(C1[3], 0.f));
            }
        if (big) {
#pragma unroll
            for (int hh = 0; hh < 2; hh++)
#pragma unroll
                for (int nt = 0; nt < 4; nt++) {
                    float C1[4];
                    mma_k8_z(C1, &A1[2], W1B[hh * 4 + nt]);
                    int s = hh * 2 + (nt >> 1), sel = nt & 1;
                    A2[1][s][2 * sel] = pkf(fmaxf(C1[0], 0.f), fmaxf(C1[1], 0.f));
                    A2[1][s][2 * sel + 1] = pkf(fmaxf(C1[2], 0.f), fmaxf(C1[3], 0.f));
                }
        }

        // ---- layer 2 via m16n8k16 + packed-fp16 epilogue ----
        const bool v0 = (rbase < cnp), v1 = (rbase + 8 < cnp);
        const bool v2 = (rbase + 16 < cnp), v3 = (rbase + 24 < cnp);
#pragma unroll
        for (int hh2 = 0; hh2 < 2; hh2++) {
            float C2a[4][4], C2b[4][4];
#pragma unroll
            for (int nt = 0; nt < 4; nt++) {
                uint2 b = W2B[(hh2 * 4 + nt) * 4];
                mma_f16_z(C2a[nt], A2[0][0], b.x, b.y);
            }
#pragma unroll
            for (int ks = 1; ks < 4; ks++)
#pragma unroll
                for (int nt = 0; nt < 4; nt++) {
                    uint2 b = W2B[(hh2 * 4 + nt) * 4 + ks];
                    mma_f16(C2a[nt], A2[0][ks], b.x, b.y);
                }
            if (big) {
#pragma unroll
                for (int nt = 0; nt < 4; nt++) {
                    uint2 b = W2B[(hh2 * 4 + nt) * 4];
                    mma_f16_z(C2b[nt], A2[1][0], b.x, b.y);
                }
#pragma unroll
                for (int ks = 1; ks < 4; ks++)
#pragma unroll
                    for (int nt = 0; nt < 4; nt++) {
                        uint2 b = W2B[(hh2 * 4 + nt) * 4 + ks];
                        mma_f16(C2b[nt], A2[1][ks], b.x, b.y);
                    }
            }
#pragma unroll
            for (int nt = 0; nt < 4; nt++) {
                unsigned best = NEGH2;
                unsigned m0 = pkf(C2a[nt][0], C2a[nt][1]);
                unsigned m1 = pkf(C2a[nt][2], C2a[nt][3]);
                if (v0) best = hmax2(best, m0);
                if (v1) best = hmax2(best, m1);
                if (big) {
                    unsigned m2v = pkf(C2b[nt][0], C2b[nt][1]);
                    unsigned m3 = pkf(C2b[nt][2], C2b[nt][3]);
                    if (v2) best = hmax2(best, m2v);
                    if (v3) best = hmax2(best, m3);
                }
#pragma unroll
                for (int off = 4; off <= 16; off <<= 1)
                    best = hmax2(best, __shfl_xor_sync(0xffffffffu, best, off));
                if (lane < 4) {
                    int t2 = hh2 * 4 + nt;
                    float2 bv = s_b2p[t2 * 4 + lane];
                    __half2 bh = *reinterpret_cast<__half2*>(&best);
                    float2 res;
                    res.x = fmaxf(__low2float(bh) + bv.x, 0.f);
                    res.y = fmaxf(__high2float(bh) + bv.y, 0.f);
                    *(float2*)(out + (size_t)cp * 64 + t2 * 8 + 2 * lane) = res;
                }
            }
        }
        __syncwarp();  // protect s_feat reuse across iterations
    }
}

extern "C" void kernel_launch(void* const* d_in, const int* in_sizes, int n_in,
                              void* d_out, int out_size) {
    const float* pillars = (const float*)d_in[0];
    const void*  coords  = d_in[1];
    const void*  npts    = d_in[2];
    const float* W1 = (const float*)d_in[3];
    const float* b1 = (const float*)d_in[4];
    const float* g1 = (const float*)d_in[5];
    const float* be1 = (const float*)d_in[6];
    const float* m1 = (const float*)d_in[7];
    const float* v1 = (const float*)d_in[8];
    const float* W2 = (const float*)d_in[9];
    const float* b2 = (const float*)d_in[10];
    const float* g2 = (const float*)d_in[11];
    const float* be2 = (const float*)d_in[12];
    const float* m2 = (const float*)d_in[13];
    const float* v2 = (const float*)d_in[14];

    int P = in_sizes[0] / 128;
    int n_words = 2 * P < 4096 ? 2 * P : 4096;

    prep_kernel<<<1, 128>>>(W1, b1, g1, be1, m1, v1, W2, b2, g2, be2, m2, v2,
                            (const unsigned*)coords, n_words);

    int grid = 3 * 152;
    int need = (P + 3) / 4;
    if (grid > need) grid = need;
    if (grid < 1) grid = 1;
    pfn_main<<<grid, 128>>>((const float4*)pillars, coords, npts, (float*)d_out, P);
}

// round 12
// speedup vs baseline: 5.5676x; 1.0735x over previous
#include <cuda_runtime.h>
#include <cuda_fp16.h>
#include <cstdint>

#define RESV 0.16f
#define XMINV (-51.2f)
#define YMINV (-51.2f)
#define EPSV 1e-5f
#define NEGV (-1.0e9f)
#define NEGH2 0xFBFFFBFFu   // fp16x2 {-65504,-65504}

// ---------------- folded weights + fragment tables ----------------
__device__ float4 g_w1pack[64];    // {Wx,Wy,Wz,Wr}*a1 per channel
__device__ float4 g_k1pack[64];    // {b1f, Wxc, Wyc, Wzm}
__device__ float2 g_b2p[32];       // bias pairs (c=2i, 2i+1)
__device__ float  g_a2[64];
__device__ unsigned g_W1frag[256]; // [n-tile 0..7][lane] m16n8k8 B frags
__device__ uint2    g_W2frag[1024];// [(n-tile*4+k-tile)][lane] m16n8k16 B frags
__device__ int g_is64;

__device__ __forceinline__ unsigned pkf(float lo, float hi) {
    unsigned r;
    asm("cvt.rn.f16x2.f32 %0, %1, %2;" : "=r"(r) : "f"(hi), "f"(lo));
    return r;
}

__global__ void prep_kernel(const float* __restrict__ W1, const float* __restrict__ b1,
                            const float* __restrict__ g1, const float* __restrict__ beta1,
                            const float* __restrict__ m1, const float* __restrict__ v1,
                            const float* __restrict__ W2, const float* __restrict__ b2,
                            const float* __restrict__ g2, const float* __restrict__ beta2,
                            const float* __restrict__ m2, const float* __restrict__ v2,
                            const unsigned* __restrict__ coords_raw, int n_words) {
    int tid = threadIdx.x;  // 128 threads
    if (tid == 0) g_is64 = 1;
    __syncthreads();
    int nz = 0;
    for (int i = 2 * tid + 1; i < n_words; i += 256) nz |= (coords_raw[i] != 0u);
    if (nz) g_is64 = 0;

    if (tid < 64) {
        int c = tid;
        float a1 = g1[c] * rsqrtf(v1[c] + EPSV);
        float w0 = W1[0*64+c], w1 = W1[1*64+c], w2v = W1[2*64+c];
        float w3 = W1[3*64+c], w4 = W1[4*64+c], w5 = W1[5*64+c];
        float w6 = W1[6*64+c], w7 = W1[7*64+c], w8 = W1[8*64+c];
        g_w1pack[c] = make_float4((w0+w4+w7)*a1, (w1+w5+w8)*a1, (w2v+w6)*a1, w3*a1);
        g_k1pack[c] = make_float4((b1[c]-m1[c])*a1 + beta1[c], (w4+w7)*a1, (w5+w8)*a1, w6*a1);
        float a2 = g2[c] * rsqrtf(v2[c] + EPSV);
        g_a2[c] = a2;
        ((float*)g_b2p)[c] = (b2[c] - m2[c]) * a2 + beta2[c];
    }
    __syncthreads();

    // W1 B-fragments (m16n8k8): n-tile t, lane l -> n=8t+l/4, k0=2(l%4)
    for (int idx = tid; idx < 256; idx += 128) {
        int t = idx >> 5, l = idx & 31;
        int n = 8 * t + (l >> 2), k0 = (l & 3) * 2;
        float4 wp = g_w1pack[n];
        float4 kp = g_k1pack[n];
        float row[8] = {wp.x, wp.y, wp.z, wp.w, -kp.y, -kp.z, -kp.w, kp.x};
        g_W1frag[idx] = pkf(row[k0], row[k0 + 1]);
    }
    // W2 B-fragments (m16n8k16): tile=(t2*4+ks), lane l -> n=8t2+l/4, j=l%4
    for (int idx = tid; idx < 1024; idx += 128) {
        int tile = idx >> 5, l = idx & 31;
        int t2 = tile >> 2, ks = tile & 3;
        int c = 8 * t2 + (l >> 2), j = l & 3;
        float a2v = g_a2[c];
        int k0 = 16 * ks + 2 * j;
        unsigned b0 = pkf(W2[k0 * 64 + c] * a2v,        W2[(k0 + 1) * 64 + c] * a2v);
        unsigned b1v = pkf(W2[(k0 + 8) * 64 + c] * a2v, W2[(k0 + 9) * 64 + c] * a2v);
        g_W2frag[idx] = make_uint2(b0, b1v);
    }
}

// ---------------- helpers ----------------
__device__ __forceinline__ uint32_t smem_u32(const void* p) {
    uint32_t a;
    asm("{ .reg .u64 t; cvta.to.shared.u64 t, %1; cvt.u32.u64 %0, t; }" : "=r"(a) : "l"(p));
    return a;
}
__device__ __forceinline__ void ldm4(unsigned* r, uint32_t a) {
    asm volatile("ldmatrix.sync.aligned.m8n8.x4.shared.b16 {%0,%1,%2,%3}, [%4];"
        : "=r"(r[0]), "=r"(r[1]), "=r"(r[2]), "=r"(r[3]) : "r"(a));
}
__device__ __forceinline__ void mma_k8_z(float* d, const unsigned* a, unsigned b0) {
    asm("mma.sync.aligned.m16n8k8.row.col.f32.f16.f16.f32 "
        "{%0,%1,%2,%3}, {%4,%5}, {%6}, {%7,%8,%9,%10};"
        : "=f"(d[0]), "=f"(d[1]), "=f"(d[2]), "=f"(d[3])
        : "r"(a[0]), "r"(a[1]), "r"(b0),
          "f"(0.f), "f"(0.f), "f"(0.f), "f"(0.f));
}
__device__ __forceinline__ void mma_f16_z(float* d, const unsigned* a, unsigned b0, unsigned b1) {
    asm("mma.sync.aligned.m16n8k16.row.col.f32.f16.f16.f32 "
        "{%0,%1,%2,%3}, {%4,%5,%6,%7}, {%8,%9}, {%10,%11,%12,%13};"
        : "=f"(d[0]), "=f"(d[1]), "=f"(d[2]), "=f"(d[3])
        : "r"(a[0]), "r"(a[1]), "r"(a[2]), "r"(a[3]), "r"(b0), "r"(b1),
          "f"(0.f), "f"(0.f), "f"(0.f), "f"(0.f));
}
__device__ __forceinline__ void mma_f16(float* c, const unsigned* a, unsigned b0, unsigned b1) {
    asm("mma.sync.aligned.m16n8k16.row.col.f32.f16.f16.f32 "
        "{%0,%1,%2,%3}, {%4,%5,%6,%7}, {%8,%9}, {%0,%1,%2,%3};"
        : "+f"(c[0]), "+f"(c[1]), "+f"(c[2]), "+f"(c[3])
        : "r"(a[0]), "r"(a[1]), "r"(a[2]), "r"(a[3]), "r"(b0), "r"(b1));
}
__device__ __forceinline__ unsigned hmax2(unsigned a, unsigned b) {
    unsigned r;
    asm("max.f16x2 %0, %1, %2;" : "=r"(r) : "r"(a), "r"(b));
    return r;
}

__device__ __forceinline__ void load_pillar(int p, int is64,
        const void* __restrict__ coords_raw, const void* __restrict__ npts_raw,
        const float4* __restrict__ pillars, int lane,
        int& np, float& xc, float& yc, float4& pt) {
    long long rw, cl;
    if (is64) {
        np = (int)((const long long*)npts_raw)[p];
        rw = ((const long long*)coords_raw)[2 * p];
        cl = ((const long long*)coords_raw)[2 * p + 1];
    } else {
        np = ((const int*)npts_raw)[p];
        rw = (long long)((const int*)coords_raw)[2 * p];
        cl = (long long)((const int*)coords_raw)[2 * p + 1];
    }
    xc = ((float)cl + 0.5f) * RESV + XMINV;
    yc = ((float)rw + 0.5f) * RESV + YMINV;
    pt = pillars[(size_t)p * 32 + lane];
}

__global__ void __launch_bounds__(128, 4)
pfn_main(const float4* __restrict__ pillars,
         const void* __restrict__ coords_raw,
         const void* __restrict__ npts_raw,
         float* __restrict__ out, int P) {
    __shared__ uint4 s_feat[128];    // 4 warps x 32 rows x 16B
    __shared__ float2 s_b2p[32];
    __shared__ uint2 s_W2[1024];     // W2 fragments, [tile][lane] layout (8KB)
    const int tid = threadIdx.x;
    const int wid = tid >> 5;
    const int lane = tid & 31;
    const int is64 = g_is64;

    if (tid < 32) s_b2p[tid] = g_b2p[tid];
    for (int i = tid; i < 1024; i += 128) s_W2[i] = g_W2frag[i];

    // W1 fragments stay in registers (8 regs)
    unsigned W1B[8];
#pragma unroll
    for (int t = 0; t < 8; t++) W1B[t] = g_W1frag[t * 32 + lane];

    const uint32_t featAddr = smem_u32(s_feat + (wid << 5)) + (uint32_t)lane * 16u;
    uint4* myfeat = s_feat + (wid << 5) + lane;
    const uint2* w2p = s_W2 + lane;   // per-lane base; tile i at w2p[i*32]
    const int rbase = lane >> 2;
    const int stride = gridDim.x * 4;
    __syncthreads();  // s_b2p / s_W2 ready

    int p = blockIdx.x * 4 + wid;
    int np = 0; float xc = 0.f, yc = 0.f; float4 pt = make_float4(0.f, 0.f, 0.f, 0.f);
    if (p < P) load_pillar(p, is64, coords_raw, npts_raw, pillars, lane, np, xc, yc, pt);

    while (p < P) {
        // ---- capture current, issue prefetch for next ----
        const int cp = p, cnp = np;
        const float cxc = xc, cyc = yc;
        const float4 cpt = pt;
        p += stride;
        if (p < P) load_pillar(p, is64, coords_raw, npts_raw, pillars, lane, np, xc, yc, pt);

        // ---- empty pillar: output all NEGV, skip compute (warp-uniform) ----
        if (cnp == 0) {
            *(float2*)(out + (size_t)cp * 64 + 2 * lane) = make_float2(NEGV, NEGV);
            continue;
        }
        const bool big = (cnp > 16);  // warp-uniform: rows 16..31 live?

        // ---- zmean ----
        float zs = (lane < cnp) ? cpt.z : 0.f;
#pragma unroll
        for (int o = 16; o; o >>= 1) zs += __shfl_xor_sync(0xffffffffu, zs, o);
        const float zm = zs / (float)cnp;

        // ---- feat row (fp16): [x,y,z,r,xc,yc,zm,1] ----
        *myfeat = make_uint4(pkf(cpt.x, cpt.y), pkf(cpt.z, cpt.w),
                             pkf(cxc, cyc), pkf(zm, 1.0f));
        __syncwarp();
        unsigned A1[4];
        ldm4(A1, featAddr);
        __syncwarp();

        // ---- layer 1 via m16n8k8; mt=1 only when rows 16..31 live ----
        unsigned A2[2][4][4];
#pragma unroll
        for (int hh = 0; hh < 2; hh++)
#pragma unroll
            for (int nt = 0; nt < 4; nt++) {
                float C1[4];
                mma_k8_z(C1, &A1[0], W1B[hh * 4 + nt]);
                int s = hh * 2 + (nt >> 1), sel = nt & 1;
                A2[0][s][2 * sel] = pkf(fmaxf(C1[0], 0.f), fmaxf(C1[1], 0.f));
                A2[0][s][2 * sel + 1] = pkf(fmaxf(C1[2], 0.f), fmaxf(C1[3], 0.f));
            }
        if (big) {
#pragma unroll
            for (int hh = 0; hh < 2; hh++)
#pragma unroll
                for (int nt = 0; nt < 4; nt++) {
                    float C1[4];
                    mma_k8_z(C1, &A1[2], W1B[hh * 4 + nt]);
                    int s = hh * 2 + (nt >> 1), sel = nt & 1;
                    A2[1][s][2 * sel] = pkf(fmaxf(C1[0], 0.f), fmaxf(C1[1], 0.f));
                    A2[1][s][2 * sel + 1] = pkf(fmaxf(C1[2], 0.f), fmaxf(C1[3], 0.f));
                }
        }

        // ---- layer 2 via m16n8k16 (B frags from smem LDS.64) + epilogue ----
        const bool v0 = (rbase < cnp), v1 = (rbase + 8 < cnp);
        const bool v2 = (rbase + 16 < cnp), v3 = (rbase + 24 < cnp);
#pragma unroll
        for (int hh2 = 0; hh2 < 2; hh2++) {
            float C2a[4][4], C2b[4][4];
#pragma unroll
            for (int nt = 0; nt < 4; nt++) {
                uint2 b = w2p[((hh2 * 4 + nt) * 4) * 32];
                mma_f16_z(C2a[nt], A2[0][0], b.x, b.y);
            }
#pragma unroll
            for (int ks = 1; ks < 4; ks++)
#pragma unroll
                for (int nt = 0; nt < 4; nt++) {
                    uint2 b = w2p[((hh2 * 4 + nt) * 4 + ks) * 32];
                    mma_f16(C2a[nt], A2[0][ks], b.x, b.y);
                }
            if (big) {
#pragma unroll
                for (int nt = 0; nt < 4; nt++) {
                    uint2 b = w2p[((hh2 * 4 + nt) * 4) * 32];
                    mma_f16_z(C2b[nt], A2[1][0], b.x, b.y);
                }
#pragma unroll
                for (int ks = 1; ks < 4; ks++)
#pragma unroll
                    for (int nt = 0; nt < 4; nt++) {
                        uint2 b = w2p[((hh2 * 4 + nt) * 4 + ks) * 32];
                        mma_f16(C2b[nt], A2[1][ks], b.x, b.y);
                    }
            }
#pragma unroll
            for (int nt = 0; nt < 4; nt++) {
                unsigned best = NEGH2;
                unsigned m0 = pkf(C2a[nt][0], C2a[nt][1]);
                unsigned m1 = pkf(C2a[nt][2], C2a[nt][3]);
                if (v0) best = hmax2(best, m0);
                if (v1) best = hmax2(best, m1);
                if (big) {
                    unsigned m2v = pkf(C2b[nt][0], C2b[nt][1]);
                    unsigned m3 = pkf(C2b[nt][2], C2b[nt][3]);
                    if (v2) best = hmax2(best, m2v);
                    if (v3) best = hmax2(best, m3);
                }
#pragma unroll
                for (int off = 4; off <= 16; off <<= 1)
                    best = hmax2(best, __shfl_xor_sync(0xffffffffu, best, off));
                if (lane < 4) {
                    int t2 = hh2 * 4 + nt;
                    float2 bv = s_b2p[t2 * 4 + lane];
                    __half2 bh = *reinterpret_cast<__half2*>(&best);
                    float2 res;
                    res.x = fmaxf(__low2float(bh) + bv.x, 0.f);
                    res.y = fmaxf(__high2float(bh) + bv.y, 0.f);
                    *(float2*)(out + (size_t)cp * 64 + t2 * 8 + 2 * lane) = res;
                }
            }
        }
        __syncwarp();  // protect s_feat reuse across iterations
    }
}

extern "C" void kernel_launch(void* const* d_in, const int* in_sizes, int n_in,
                              void* d_out, int out_size) {
    const float* pillars = (const float*)d_in[0];
    const void*  coords  = d_in[1];
    const void*  npts    = d_in[2];
    const float* W1 = (const float*)d_in[3];
    const float* b1 = (const float*)d_in[4];
    const float* g1 = (const float*)d_in[5];
    const float* be1 = (const float*)d_in[6];
    const float* m1 = (const float*)d_in[7];
    const float* v1 = (const float*)d_in[8];
    const float* W2 = (const float*)d_in[9];
    const float* b2 = (const float*)d_in[10];
    const float* g2 = (const float*)d_in[11];
    const float* be2 = (const float*)d_in[12];
    const float* m2 = (const float*)d_in[13];
    const float* v2 = (const float*)d_in[14];

    int P = in_sizes[0] / 128;
    int n_words = 2 * P < 4096 ? 2 * P : 4096;

    prep_kernel<<<1, 128>>>(W1, b1, g1, be1, m1, v1, W2, b2, g2, be2, m2, v2,
                            (const unsigned*)coords, n_words);

    int grid = 4 * 152;
    int need = (P + 3) / 4;
    if (grid > need) grid = need;
    if (grid < 1) grid = 1;
    pfn_main<<<grid, 128>>>((const float4*)pillars, coords, npts, (float*)d_out, P);
}